// round 1
// baseline (speedup 1.0000x reference)
#include <cuda_runtime.h>
#include <math.h>
#include <stdint.h>

#define NN 50000
#define EE 800000
#define HH 64
#define NLYR 3
#define NCLS 10
#define NGR 64
#define KF 576           // folded GEMM K: 64 (x) + 256 (src agg) + 256 (ea agg)
#define JW 192           // folded GEMM output cols: [plain | amp | att] x 64

// ------------------------- scratch (device globals, no allocs) ---------------
__device__ __align__(128) float g_x[NN * HH];        // current node features
__device__ __align__(128) float g_h[NN * HH];        // pre-BN layer output
__device__ __align__(128) float g_sagg[NN * 256];    // per-layer src aggregates (mean|mn|mx|std)
__device__ __align__(128) float g_eagg[NN * 256];    // one-time ea aggregates
__device__ __align__(128) float g_Wp[NLYR * KF * JW];// folded weights
__device__ float g_cstd[NLYR * JW];                  // std-dst constant contribution
__device__ int   g_degI[NN];
__device__ int   g_incl[NN];
__device__ int   g_bsumI[256];
__device__ int   g_boff[256];
__device__ int   g_rowptr[NN];
__device__ int   g_cursor[NN];
__device__ int   g_csrc[EE];
__device__ int   g_ceid[EE];
__device__ float g_has[NN];
__device__ float g_logdeg[NN];
__device__ float g_amp[NN];
__device__ float g_att[NN];
__device__ float g_logsum;
__device__ float g_bnsum[HH];
__device__ float g_bnss[HH];
__device__ float g_pool[NGR * HH];
__device__ float g_cnt[NGR];

// ------------------------------- kernels -------------------------------------

__global__ void k_init() {
    int i = blockIdx.x * 256 + threadIdx.x;
    if (i < NN) g_degI[i] = 0;
    if (i < NGR * HH) g_pool[i] = 0.f;
    if (i < NGR) g_cnt[i] = 0.f;
    if (i == 0) g_logsum = 0.f;
}

// x = x_in @ node_w + node_b   (64x64)
__global__ void k_nodeenc(const float* __restrict__ xin,
                          const float* __restrict__ nw,
                          const float* __restrict__ nb) {
    __shared__ float Ws[64 * 64];
    __shared__ float Xs[64 * 64];
    int t = threadIdx.x;
    int n0 = blockIdx.x * 64;
    for (int i = t; i < 4096; i += 256) Ws[i] = nw[i];
    for (int i = t; i < 4096; i += 256) {
        int r = i >> 6, k = i & 63;
        int n = n0 + r;
        Xs[i] = (n < NN) ? xin[n * 64 + k] : 0.f;
    }
    __syncthreads();
    for (int p = 0; p < 16; p++) {
        int o = t + p * 256;
        int r = o >> 6, d = o & 63;
        float acc = nb[d];
#pragma unroll
        for (int k = 0; k < 64; k++) acc += Xs[r * 64 + k] * Ws[k * 64 + d];
        int n = n0 + r;
        if (n < NN) g_x[n * 64 + d] = acc;
    }
}

__global__ void k_deghist(const int* __restrict__ ei) {
    int e = blockIdx.x * 256 + threadIdx.x;
    if (e < EE) atomicAdd(&g_degI[ei[EE + e]], 1);
}

__global__ void k_scanA() {
    __shared__ int sh[256];
    int t = threadIdx.x;
    int n = blockIdx.x * 256 + t;
    int v = (n < NN) ? g_degI[n] : 0;
    sh[t] = v;
    __syncthreads();
    for (int off = 1; off < 256; off <<= 1) {
        int u = (t >= off) ? sh[t - off] : 0;
        __syncthreads();
        sh[t] += u;
        __syncthreads();
    }
    if (n < NN) g_incl[n] = sh[t];
    if (t == 255) g_bsumI[blockIdx.x] = sh[255];
}

__global__ void k_scanB(int nb) {
    __shared__ int sh[256];
    int t = threadIdx.x;
    int v = (t < nb) ? g_bsumI[t] : 0;
    sh[t] = v;
    __syncthreads();
    for (int off = 1; off < 256; off <<= 1) {
        int u = (t >= off) ? sh[t - off] : 0;
        __syncthreads();
        sh[t] += u;
        __syncthreads();
    }
    g_boff[t] = sh[t] - v;  // exclusive
}

__global__ void k_scanC() {
    int n = blockIdx.x * 256 + threadIdx.x;
    if (n < NN) {
        int rp = g_boff[n >> 8] + g_incl[n] - g_degI[n];
        g_rowptr[n] = rp;
        g_cursor[n] = rp;
    }
}

__global__ void k_csr(const int* __restrict__ ei) {
    int e = blockIdx.x * 256 + threadIdx.x;
    if (e < EE) {
        int dst = ei[EE + e];
        int p = atomicAdd(&g_cursor[dst], 1);
        g_csrc[p] = ei[e];
        g_ceid[p] = e;
    }
}

__global__ void k_degstuff() {
    __shared__ float sh[256];
    int t = threadIdx.x;
    int n = blockIdx.x * 256 + t;
    float part = 0.f;
    if (n < NN) {
        int d = g_degI[n];
        float df = (float)d;
        float degc = fmaxf(df, 1.f);
        g_has[n] = (d > 0) ? 1.f : 0.f;
        float ld = logf(degc + 1.f);
        g_logdeg[n] = ld;
        part = logf(df + 1.f);
    }
    sh[t] = part;
    __syncthreads();
    for (int off = 128; off; off >>= 1) {
        if (t < off) sh[t] += sh[t + off];
        __syncthreads();
    }
    if (t == 0) atomicAdd(&g_logsum, sh[0]);
}

__global__ void k_ampatt() {
    int n = blockIdx.x * 256 + threadIdx.x;
    if (n < NN) {
        float avg = g_logsum * (1.f / (float)NN);
        float ld = g_logdeg[n];
        g_amp[n] = ld / avg;
        g_att[n] = avg / ld;
    }
}

// one-time edge-attr aggregation: ea = attr@edge_w + edge_b computed on the fly
__global__ void k_eagg(const float* __restrict__ eattr,
                       const float* __restrict__ ew,
                       const float* __restrict__ eb) {
    __shared__ float Ws[16 * 64];
    __shared__ float Bs[64];
    int t = threadIdx.x;
    for (int i = t; i < 1024; i += 256) Ws[i] = ew[i];
    if (t < 64) Bs[t] = eb[t];
    __syncthreads();
    int w = t >> 5, lane = t & 31;
    int n = blockIdx.x * 8 + w;
    if (n >= NN) return;
    int start = g_rowptr[n], deg = g_degI[n];
    int d0 = lane, d1 = lane + 32;
    float b0 = Bs[d0], b1 = Bs[d1];
    float s0 = 0.f, ss0 = 0.f, mx0 = -1e30f, mn0 = 1e30f;
    float s1 = 0.f, ss1 = 0.f, mx1 = -1e30f, mn1 = 1e30f;
    for (int i = 0; i < deg; i++) {
        int e = g_ceid[start + i];
        float av = (lane < 16) ? eattr[(size_t)e * 16 + lane] : 0.f;
        float v0 = b0, v1 = b1;
#pragma unroll
        for (int k = 0; k < 16; k++) {
            float a = __shfl_sync(0xffffffffu, av, k);
            v0 += a * Ws[k * 64 + d0];
            v1 += a * Ws[k * 64 + d1];
        }
        s0 += v0; ss0 += v0 * v0; mx0 = fmaxf(mx0, v0); mn0 = fminf(mn0, v0);
        s1 += v1; ss1 += v1 * v1; mx1 = fmaxf(mx1, v1); mn1 = fminf(mn1, v1);
    }
    float inv = 1.f / fmaxf((float)deg, 1.f);
    float m0 = s0 * inv, m1 = s1 * inv;
    float sd0 = sqrtf(fmaxf(ss0 * inv - m0 * m0, 0.f) + 1e-5f);
    float sd1 = sqrtf(fmaxf(ss1 * inv - m1 * m1, 0.f) + 1e-5f);
    if (deg == 0) { mx0 = 0.f; mn0 = 0.f; mx1 = 0.f; mn1 = 0.f; }
    float* o = &g_eagg[(size_t)n * 256];
    o[d0] = m0;        o[d1] = m1;
    o[64 + d0] = mn0;  o[64 + d1] = mn1;
    o[128 + d0] = mx0; o[128 + d1] = mx1;
    o[192 + d0] = sd0; o[192 + d1] = sd1;
}

// per-layer src aggregation (x is L2-resident)
__global__ void k_srcagg() {
    int t = threadIdx.x;
    int w = t >> 5, lane = t & 31;
    int n = blockIdx.x * 8 + w;
    if (n >= NN) return;
    int start = g_rowptr[n], deg = g_degI[n];
    int d0 = lane, d1 = lane + 32;
    float s0 = 0.f, ss0 = 0.f, mx0 = -1e30f, mn0 = 1e30f;
    float s1 = 0.f, ss1 = 0.f, mx1 = -1e30f, mn1 = 1e30f;
    for (int i = 0; i < deg; i++) {
        int s = g_csrc[start + i];
        float v0 = g_x[(size_t)s * 64 + d0];
        float v1 = g_x[(size_t)s * 64 + d1];
        s0 += v0; ss0 += v0 * v0; mx0 = fmaxf(mx0, v0); mn0 = fminf(mn0, v0);
        s1 += v1; ss1 += v1 * v1; mx1 = fmaxf(mx1, v1); mn1 = fminf(mn1, v1);
    }
    float inv = 1.f / fmaxf((float)deg, 1.f);
    float m0 = s0 * inv, m1 = s1 * inv;
    float sd0 = sqrtf(fmaxf(ss0 * inv - m0 * m0, 0.f) + 1e-5f);
    float sd1 = sqrtf(fmaxf(ss1 * inv - m1 * m1, 0.f) + 1e-5f);
    if (deg == 0) { mx0 = 0.f; mn0 = 0.f; mx1 = 0.f; mn1 = 0.f; }
    float* o = &g_sagg[(size_t)n * 256];
    o[d0] = m0;        o[d1] = m1;
    o[64 + d0] = mn0;  o[64 + d1] = mn1;
    o[128 + d0] = mx0; o[128 + d1] = mx1;
    o[192 + d0] = sd0; o[192 + d1] = sd1;
}

// fold conv_w [2304,64] -> W' [576,192]
__global__ void k_wprep(const float* __restrict__ cw) {
    int idx = blockIdx.x * 256 + threadIdx.x;
    if (idx >= NLYR * KF * JW) return;
    int l = idx / (KF * JW);
    int r = idx % (KF * JW);
    int k = r / JW;
    int j = r % JW;
    int blk = j >> 6, c = j & 63;
    size_t base = (size_t)l * 2304 * 64;
    int R = blk * 768;
    float w;
    if (k < 64) {
        int d = k;
        w = cw[base + (size_t)(R + d) * 64 + c]
          + cw[base + (size_t)(R + 192 + d) * 64 + c]
          + cw[base + (size_t)(R + 384 + d) * 64 + c];
    } else if (k < 128) { int d = k - 64;  w = cw[base + (size_t)(R + 64 + d) * 64 + c]; }
    else if (k < 192)   { int d = k - 128; w = cw[base + (size_t)(R + 256 + d) * 64 + c]; }
    else if (k < 256)   { int d = k - 192; w = cw[base + (size_t)(R + 448 + d) * 64 + c]; }
    else if (k < 320)   { int d = k - 256; w = cw[base + (size_t)(R + 640 + d) * 64 + c]; }
    else if (k < 384)   { int d = k - 320; w = cw[base + (size_t)(R + 128 + d) * 64 + c]; }
    else if (k < 448)   { int d = k - 384; w = cw[base + (size_t)(R + 320 + d) * 64 + c]; }
    else if (k < 512)   { int d = k - 448; w = cw[base + (size_t)(R + 512 + d) * 64 + c]; }
    else                { int d = k - 512; w = cw[base + (size_t)(R + 704 + d) * 64 + c]; }
    g_Wp[idx] = w;
}

__global__ void k_cstd(const float* __restrict__ cw) {
    int idx = blockIdx.x * 64 + threadIdx.x;
    if (idx >= NLYR * JW) return;
    int l = idx / JW;
    int j = idx % JW;
    int blk = j >> 6, c = j & 63;
    size_t base = (size_t)l * 2304 * 64;
    int R = blk * 768 + 576;
    float s = 0.f;
    for (int d = 0; d < 64; d++) s += cw[base + (size_t)(R + d) * 64 + c];
    g_cstd[idx] = sqrtf(1e-5f) * s;
}

// fused GEMM: h[N,64] = combine( f[N,576] @ W'[576,192] ) + biases
#define BM 128
#define ASTR 132
__global__ void k_gemm(int l, const float* __restrict__ convb) {
    __shared__ float As[16 * ASTR];
    __shared__ float Bs[16 * JW];
    int t = threadIdx.x;
    int ty = t >> 4, tx = t & 15;
    int rowBase = blockIdx.x * BM;
    float acc[8][12];
#pragma unroll
    for (int r = 0; r < 8; r++)
#pragma unroll
        for (int i = 0; i < 12; i++) acc[r][i] = 0.f;
    const float* Wl = g_Wp + (size_t)l * KF * JW;

    for (int kt = 0; kt < KF / 16; kt++) {
        int k0 = kt * 16;
        const float* src;
        int stride;
        bool useHas = false;
        if (k0 < 64)       { src = g_x + k0;           stride = 64;  useHas = true; }
        else if (k0 < 320) { src = g_sagg + (k0 - 64); stride = 256; }
        else               { src = g_eagg + (k0 - 320); stride = 256; }
#pragma unroll
        for (int p = 0; p < 2; p++) {
            int idx = t + p * 256;
            int row = idx >> 2, c4 = idx & 3;
            int gr = rowBase + row;
            float4 v = make_float4(0.f, 0.f, 0.f, 0.f);
            if (gr < NN) {
                v = *(const float4*)(src + (size_t)gr * stride + c4 * 4);
                if (useHas) {
                    float m = g_has[gr];
                    v.x *= m; v.y *= m; v.z *= m; v.w *= m;
                }
            }
            As[(c4 * 4 + 0) * ASTR + row] = v.x;
            As[(c4 * 4 + 1) * ASTR + row] = v.y;
            As[(c4 * 4 + 2) * ASTR + row] = v.z;
            As[(c4 * 4 + 3) * ASTR + row] = v.w;
        }
#pragma unroll
        for (int p = 0; p < 3; p++) {
            int idx = t + p * 256;
            int kr = idx / 48, c4 = idx % 48;
            float4 v = *(const float4*)(Wl + (size_t)(k0 + kr) * JW + c4 * 4);
            *(float4*)(Bs + kr * JW + c4 * 4) = v;
        }
        __syncthreads();
#pragma unroll
        for (int kk = 0; kk < 16; kk++) {
            float a[8];
#pragma unroll
            for (int r = 0; r < 8; r++) a[r] = As[kk * ASTR + ty * 8 + r];
            float4 b0 = *(float4*)(Bs + kk * JW + tx * 4);
            float4 b1 = *(float4*)(Bs + kk * JW + 64 + tx * 4);
            float4 b2 = *(float4*)(Bs + kk * JW + 128 + tx * 4);
#pragma unroll
            for (int r = 0; r < 8; r++) {
                acc[r][0] += a[r] * b0.x; acc[r][1] += a[r] * b0.y;
                acc[r][2] += a[r] * b0.z; acc[r][3] += a[r] * b0.w;
                acc[r][4] += a[r] * b1.x; acc[r][5] += a[r] * b1.y;
                acc[r][6] += a[r] * b1.z; acc[r][7] += a[r] * b1.w;
                acc[r][8] += a[r] * b2.x; acc[r][9] += a[r] * b2.y;
                acc[r][10] += a[r] * b2.z; acc[r][11] += a[r] * b2.w;
            }
        }
        __syncthreads();
    }
#pragma unroll
    for (int r = 0; r < 8; r++) {
        int n = rowBase + ty * 8 + r;
        if (n >= NN) continue;
        float amp = g_amp[n], att = g_att[n];
#pragma unroll
        for (int i = 0; i < 4; i++) {
            int c = tx * 4 + i;
            float h = acc[r][i] + amp * acc[r][4 + i] + att * acc[r][8 + i]
                    + g_cstd[l * JW + c] + amp * g_cstd[l * JW + 64 + c]
                    + att * g_cstd[l * JW + 128 + c]
                    + convb[l * 64 + c];
            g_h[(size_t)n * 64 + c] = h;
        }
    }
}

__global__ void k_bnzero() {
    int t = threadIdx.x;
    if (t < HH) { g_bnsum[t] = 0.f; g_bnss[t] = 0.f; }
}

__global__ void k_bnstats() {
    __shared__ float sh[512];
    int t = threadIdx.x;
    int c = t & 63, rg = t >> 6;
    float s = 0.f, ss = 0.f;
    int r0 = blockIdx.x * 256;
    for (int r = r0 + rg; r < r0 + 256 && r < NN; r += 4) {
        float v = g_h[(size_t)r * 64 + c];
        s += v;
        ss += v * v;
    }
    sh[t] = s; sh[256 + t] = ss;
    __syncthreads();
    if (rg == 0) {
        float S = sh[c] + sh[64 + c] + sh[128 + c] + sh[192 + c];
        float SS = sh[256 + c] + sh[320 + c] + sh[384 + c] + sh[448 + c];
        atomicAdd(&g_bnsum[c], S);
        atomicAdd(&g_bnss[c], SS);
    }
}

__global__ void k_bnapply(int l, const float* __restrict__ bg, const float* __restrict__ bb) {
    int idx = blockIdx.x * 256 + threadIdx.x;
    if (idx >= NN * HH) return;
    int c = idx & 63;
    float mu = g_bnsum[c] * (1.f / (float)NN);
    float var = fmaxf(g_bnss[c] * (1.f / (float)NN) - mu * mu, 0.f);
    float rs = rsqrtf(var + 1e-5f);
    float v = (g_h[idx] - mu) * rs * bg[l * 64 + c] + bb[l * 64 + c];
    g_x[idx] = fmaxf(v, 0.f) + g_x[idx];
}

__global__ void k_pool(const int* __restrict__ batch) {
    int idx = blockIdx.x * 256 + threadIdx.x;
    if (idx >= NN * HH) return;
    int n = idx >> 6, c = idx & 63;
    int b = batch[n];
    atomicAdd(&g_pool[b * 64 + c], g_x[idx]);
    if (c == 0) atomicAdd(&g_cnt[b], 1.f);
}

__global__ void k_fc(const float* __restrict__ w1, const float* __restrict__ b1,
                     const float* __restrict__ w2, const float* __restrict__ b2,
                     const float* __restrict__ w3, const float* __restrict__ b3,
                     float* __restrict__ out) {
    int g = threadIdx.x;
    if (g >= NGR) return;
    float v[64];
    float cnt = fmaxf(g_cnt[g], 1.f);
    float inv = 1.f / cnt;
    for (int d = 0; d < 64; d++) v[d] = g_pool[g * 64 + d] * inv;
    float h1[32];
    for (int o = 0; o < 32; o++) {
        float a = b1[o];
        for (int k = 0; k < 64; k++) a += v[k] * w1[k * 32 + o];
        h1[o] = fmaxf(a, 0.f);
    }
    float h2[16];
    for (int o = 0; o < 16; o++) {
        float a = b2[o];
        for (int k = 0; k < 32; k++) a += h1[k] * w2[k * 16 + o];
        h2[o] = fmaxf(a, 0.f);
    }
    for (int o = 0; o < NCLS; o++) {
        float a = b3[o];
        for (int k = 0; k < 16; k++) a += h2[k] * w3[k * 10 + o];
        out[g * NCLS + o] = a;
    }
}

// ------------------------------- launcher ------------------------------------
extern "C" void kernel_launch(void* const* d_in, const int* in_sizes, int n_in,
                              void* d_out, int out_size) {
    const float* xin   = (const float*)d_in[0];
    const int*   ei    = (const int*)d_in[1];
    const int*   batch = (const int*)d_in[2];
    const float* eattr = (const float*)d_in[3];
    const float* nw    = (const float*)d_in[4];
    const float* nb    = (const float*)d_in[5];
    const float* ew    = (const float*)d_in[6];
    const float* eb    = (const float*)d_in[7];
    const float* cw    = (const float*)d_in[8];
    const float* cb    = (const float*)d_in[9];
    const float* bg    = (const float*)d_in[10];
    const float* bb    = (const float*)d_in[11];
    const float* f1w   = (const float*)d_in[12];
    const float* f1b   = (const float*)d_in[13];
    const float* f2w   = (const float*)d_in[14];
    const float* f2b   = (const float*)d_in[15];
    const float* f3w   = (const float*)d_in[16];
    const float* f3b   = (const float*)d_in[17];
    float* out = (float*)d_out;

    const int NB_N = (NN + 255) / 256;           // 196
    const int NB_E = (EE + 255) / 256;
    const int NB_NE = (NN + 63) / 64;            // nodeenc blocks
    const int NB_W = (NN + 7) / 8;               // warp-per-node blocks
    const int NB_ND = (NN * HH + 255) / 256;

    k_init<<<NB_N, 256>>>();
    k_nodeenc<<<NB_NE, 256>>>(xin, nw, nb);
    k_deghist<<<NB_E, 256>>>(ei);
    k_scanA<<<NB_N, 256>>>();
    k_scanB<<<1, 256>>>(NB_N);
    k_scanC<<<NB_N, 256>>>();
    k_csr<<<NB_E, 256>>>(ei);
    k_degstuff<<<NB_N, 256>>>();
    k_ampatt<<<NB_N, 256>>>();
    k_eagg<<<NB_W, 256>>>(eattr, ew, eb);
    k_wprep<<<(NLYR * KF * JW + 255) / 256, 256>>>(cw);
    k_cstd<<<(NLYR * JW + 63) / 64, 64>>>(cw);

    for (int l = 0; l < NLYR; l++) {
        k_srcagg<<<NB_W, 256>>>();
        k_gemm<<<(NN + BM - 1) / BM, 256>>>(l, cb);
        k_bnzero<<<1, 64>>>();
        k_bnstats<<<NB_N, 256>>>();
        k_bnapply<<<NB_ND, 256>>>(l, bg, bb);
    }

    k_pool<<<NB_ND, 256>>>(batch);
    k_fc<<<1, 64>>>(f1w, f1b, f2w, f2b, f3w, f3b, out);
}

// round 6
// speedup vs baseline: 1.4707x; 1.4707x over previous
#include <cuda_runtime.h>
#include <cuda_bf16.h>
#include <math.h>
#include <stdint.h>

#define NN 50000
#define EE 800000
#define HH 64
#define NLYR 3
#define NCLS 10
#define NGR 64
#define KF 576           // folded GEMM K: 64 (x) + 256 (src agg) + 256 (ea agg)
#define JW 192           // folded GEMM output cols: [plain | amp | att] x 64
#define KSTEPS 36        // KF / 16

// ------------------------- scratch (device globals, no allocs) ---------------
__device__ __align__(128) float g_x[NN * HH];        // current node features
__device__ __align__(128) float g_h[NN * HH];        // pre-BN layer output
__device__ __align__(128) float g_sagg[NN * 256];    // per-layer src aggregates (mean|mn|mx|std)
__device__ __align__(128) float g_eagg[NN * 256];    // one-time ea aggregates
// folded weights, bf16 hi/lo, tiled: [l][kstep][hl][n=192][kk=16]
__device__ __align__(128) __nv_bfloat16 g_Wb[NLYR * KSTEPS * 2 * 192 * 16];
__device__ float g_cstd[NLYR * JW];                  // std-dst constant contribution
__device__ int   g_degI[NN];
__device__ int   g_incl[NN];
__device__ int   g_bsumI[256];
__device__ int   g_boff[256];
__device__ int   g_rowptr[NN];
__device__ int   g_cursor[NN];
__device__ int   g_csrc[EE];
__device__ int   g_ceid[EE];
__device__ float g_has[NN];
__device__ float g_logdeg[NN];
__device__ float g_amp[NN];
__device__ float g_att[NN];
__device__ float g_logsum;
__device__ float g_bnsum[HH];
__device__ float g_bnss[HH];
__device__ float g_pool[NGR * HH];
__device__ float g_cnt[NGR];

// ------------------------------- kernels -------------------------------------

__global__ void k_init() {
    int i = blockIdx.x * 256 + threadIdx.x;
    if (i < NN) g_degI[i] = 0;
    if (i < NGR * HH) g_pool[i] = 0.f;
    if (i < NGR) g_cnt[i] = 0.f;
    if (i == 0) g_logsum = 0.f;
}

// x = x_in @ node_w + node_b   (64x64)
__global__ void k_nodeenc(const float* __restrict__ xin,
                          const float* __restrict__ nw,
                          const float* __restrict__ nb) {
    __shared__ float Ws[64 * 64];
    __shared__ float Xs[64 * 64];
    int t = threadIdx.x;
    int n0 = blockIdx.x * 64;
    for (int i = t; i < 4096; i += 256) Ws[i] = nw[i];
    for (int i = t; i < 4096; i += 256) {
        int r = i >> 6, k = i & 63;
        int n = n0 + r;
        Xs[i] = (n < NN) ? xin[n * 64 + k] : 0.f;
    }
    __syncthreads();
    for (int p = 0; p < 16; p++) {
        int o = t + p * 256;
        int r = o >> 6, d = o & 63;
        float acc = nb[d];
#pragma unroll
        for (int k = 0; k < 64; k++) acc += Xs[r * 64 + k] * Ws[k * 64 + d];
        int n = n0 + r;
        if (n < NN) g_x[n * 64 + d] = acc;
    }
}

__global__ void k_deghist(const int* __restrict__ ei) {
    int e = blockIdx.x * 256 + threadIdx.x;
    if (e < EE) atomicAdd(&g_degI[ei[EE + e]], 1);
}

__global__ void k_scanA() {
    __shared__ int sh[256];
    int t = threadIdx.x;
    int n = blockIdx.x * 256 + t;
    int v = (n < NN) ? g_degI[n] : 0;
    sh[t] = v;
    __syncthreads();
    for (int off = 1; off < 256; off <<= 1) {
        int u = (t >= off) ? sh[t - off] : 0;
        __syncthreads();
        sh[t] += u;
        __syncthreads();
    }
    if (n < NN) g_incl[n] = sh[t];
    if (t == 255) g_bsumI[blockIdx.x] = sh[255];
}

__global__ void k_scanB(int nb) {
    __shared__ int sh[256];
    int t = threadIdx.x;
    int v = (t < nb) ? g_bsumI[t] : 0;
    sh[t] = v;
    __syncthreads();
    for (int off = 1; off < 256; off <<= 1) {
        int u = (t >= off) ? sh[t - off] : 0;
        __syncthreads();
        sh[t] += u;
        __syncthreads();
    }
    g_boff[t] = sh[t] - v;  // exclusive
}

__global__ void k_scanC() {
    int n = blockIdx.x * 256 + threadIdx.x;
    if (n < NN) {
        int rp = g_boff[n >> 8] + g_incl[n] - g_degI[n];
        g_rowptr[n] = rp;
        g_cursor[n] = rp;
    }
}

__global__ void k_csr(const int* __restrict__ ei) {
    int e = blockIdx.x * 256 + threadIdx.x;
    if (e < EE) {
        int dst = ei[EE + e];
        int p = atomicAdd(&g_cursor[dst], 1);
        g_csrc[p] = ei[e];
        g_ceid[p] = e;
    }
}

__global__ void k_degstuff() {
    __shared__ float sh[256];
    int t = threadIdx.x;
    int n = blockIdx.x * 256 + t;
    float part = 0.f;
    if (n < NN) {
        int d = g_degI[n];
        float df = (float)d;
        float degc = fmaxf(df, 1.f);
        g_has[n] = (d > 0) ? 1.f : 0.f;
        float ld = logf(degc + 1.f);
        g_logdeg[n] = ld;
        part = logf(df + 1.f);
    }
    sh[t] = part;
    __syncthreads();
    for (int off = 128; off; off >>= 1) {
        if (t < off) sh[t] += sh[t + off];
        __syncthreads();
    }
    if (t == 0) atomicAdd(&g_logsum, sh[0]);
}

__global__ void k_ampatt() {
    int n = blockIdx.x * 256 + threadIdx.x;
    if (n < NN) {
        float avg = g_logsum * (1.f / (float)NN);
        float ld = g_logdeg[n];
        g_amp[n] = ld / avg;
        g_att[n] = avg / ld;
    }
}

// one-time edge-attr aggregation: ea = attr@edge_w + edge_b computed on the fly
__global__ void k_eagg(const float* __restrict__ eattr,
                       const float* __restrict__ ew,
                       const float* __restrict__ eb) {
    __shared__ float Ws[16 * 64];
    __shared__ float Bs[64];
    int t = threadIdx.x;
    for (int i = t; i < 1024; i += 256) Ws[i] = ew[i];
    if (t < 64) Bs[t] = eb[t];
    __syncthreads();
    int w = t >> 5, lane = t & 31;
    int n = blockIdx.x * 8 + w;
    if (n >= NN) return;
    int start = g_rowptr[n], deg = g_degI[n];
    int d0 = lane, d1 = lane + 32;
    float b0 = Bs[d0], b1 = Bs[d1];
    float s0 = 0.f, ss0 = 0.f, mx0 = -1e30f, mn0 = 1e30f;
    float s1 = 0.f, ss1 = 0.f, mx1 = -1e30f, mn1 = 1e30f;
    for (int i = 0; i < deg; i++) {
        int e = g_ceid[start + i];
        float av = (lane < 16) ? eattr[(size_t)e * 16 + lane] : 0.f;
        float v0 = b0, v1 = b1;
#pragma unroll
        for (int k = 0; k < 16; k++) {
            float a = __shfl_sync(0xffffffffu, av, k);
            v0 += a * Ws[k * 64 + d0];
            v1 += a * Ws[k * 64 + d1];
        }
        s0 += v0; ss0 += v0 * v0; mx0 = fmaxf(mx0, v0); mn0 = fminf(mn0, v0);
        s1 += v1; ss1 += v1 * v1; mx1 = fmaxf(mx1, v1); mn1 = fminf(mn1, v1);
    }
    float inv = 1.f / fmaxf((float)deg, 1.f);
    float m0 = s0 * inv, m1 = s1 * inv;
    float sd0 = sqrtf(fmaxf(ss0 * inv - m0 * m0, 0.f) + 1e-5f);
    float sd1 = sqrtf(fmaxf(ss1 * inv - m1 * m1, 0.f) + 1e-5f);
    if (deg == 0) { mx0 = 0.f; mn0 = 0.f; mx1 = 0.f; mn1 = 0.f; }
    float* o = &g_eagg[(size_t)n * 256];
    o[d0] = m0;        o[d1] = m1;
    o[64 + d0] = mn0;  o[64 + d1] = mn1;
    o[128 + d0] = mx0; o[128 + d1] = mx1;
    o[192 + d0] = sd0; o[192 + d1] = sd1;
}

// per-layer src aggregation (x is L2-resident)
__global__ void k_srcagg() {
    int t = threadIdx.x;
    int w = t >> 5, lane = t & 31;
    int n = blockIdx.x * 8 + w;
    if (n >= NN) return;
    int start = g_rowptr[n], deg = g_degI[n];
    int d0 = lane, d1 = lane + 32;
    float s0 = 0.f, ss0 = 0.f, mx0 = -1e30f, mn0 = 1e30f;
    float s1 = 0.f, ss1 = 0.f, mx1 = -1e30f, mn1 = 1e30f;
    for (int i = 0; i < deg; i++) {
        int s = g_csrc[start + i];
        float v0 = g_x[(size_t)s * 64 + d0];
        float v1 = g_x[(size_t)s * 64 + d1];
        s0 += v0; ss0 += v0 * v0; mx0 = fmaxf(mx0, v0); mn0 = fminf(mn0, v0);
        s1 += v1; ss1 += v1 * v1; mx1 = fmaxf(mx1, v1); mn1 = fminf(mn1, v1);
    }
    float inv = 1.f / fmaxf((float)deg, 1.f);
    float m0 = s0 * inv, m1 = s1 * inv;
    float sd0 = sqrtf(fmaxf(ss0 * inv - m0 * m0, 0.f) + 1e-5f);
    float sd1 = sqrtf(fmaxf(ss1 * inv - m1 * m1, 0.f) + 1e-5f);
    if (deg == 0) { mx0 = 0.f; mn0 = 0.f; mx1 = 0.f; mn1 = 0.f; }
    float* o = &g_sagg[(size_t)n * 256];
    o[d0] = m0;        o[d1] = m1;
    o[64 + d0] = mn0;  o[64 + d1] = mn1;
    o[128 + d0] = mx0; o[128 + d1] = mx1;
    o[192 + d0] = sd0; o[192 + d1] = sd1;
}

// fold conv_w [2304,64] -> W' [576,192], split into bf16 hi/lo, tile for GEMM
__global__ void k_wprep(const float* __restrict__ cw) {
    int idx = blockIdx.x * 256 + threadIdx.x;
    if (idx >= NLYR * KF * JW) return;
    int l = idx / (KF * JW);
    int r = idx % (KF * JW);
    int k = r / JW;
    int j = r % JW;
    int blk = j >> 6, c = j & 63;
    size_t base = (size_t)l * 2304 * 64;
    int R = blk * 768;
    float w;
    if (k < 64) {
        int d = k;
        w = cw[base + (size_t)(R + d) * 64 + c]
          + cw[base + (size_t)(R + 192 + d) * 64 + c]
          + cw[base + (size_t)(R + 384 + d) * 64 + c];
    } else if (k < 128) { int d = k - 64;  w = cw[base + (size_t)(R + 64 + d) * 64 + c]; }
    else if (k < 192)   { int d = k - 128; w = cw[base + (size_t)(R + 256 + d) * 64 + c]; }
    else if (k < 256)   { int d = k - 192; w = cw[base + (size_t)(R + 448 + d) * 64 + c]; }
    else if (k < 320)   { int d = k - 256; w = cw[base + (size_t)(R + 640 + d) * 64 + c]; }
    else if (k < 384)   { int d = k - 320; w = cw[base + (size_t)(R + 128 + d) * 64 + c]; }
    else if (k < 448)   { int d = k - 384; w = cw[base + (size_t)(R + 320 + d) * 64 + c]; }
    else if (k < 512)   { int d = k - 448; w = cw[base + (size_t)(R + 512 + d) * 64 + c]; }
    else                { int d = k - 512; w = cw[base + (size_t)(R + 704 + d) * 64 + c]; }
    // split and write tiled bf16: [l][kstep][hl][n=192][kk=16]
    __nv_bfloat16 hi = __float2bfloat16_rn(w);
    float lof = w - __bfloat162float(hi);
    __nv_bfloat16 lo = __float2bfloat16_rn(lof);
    int kstep = k >> 4, kk = k & 15;
    size_t ob = ((size_t)(l * KSTEPS + kstep) * 2) * 3072 + (size_t)j * 16 + kk;
    g_Wb[ob] = hi;
    g_Wb[ob + 3072] = lo;
}

__global__ void k_cstd(const float* __restrict__ cw) {
    int idx = blockIdx.x * 64 + threadIdx.x;
    if (idx >= NLYR * JW) return;
    int l = idx / JW;
    int j = idx % JW;
    int blk = j >> 6, c = j & 63;
    size_t base = (size_t)l * 2304 * 64;
    int R = blk * 768 + 576;
    float s = 0.f;
    for (int d = 0; d < 64; d++) s += cw[base + (size_t)(R + d) * 64 + c];
    g_cstd[idx] = sqrtf(1e-5f) * s;
}

// --------------------- tensor-core folded GEMM -------------------------------
__device__ __forceinline__ void mma16816(float* c, unsigned a0, unsigned a1,
                                         unsigned a2, unsigned a3,
                                         unsigned b0, unsigned b1) {
    asm volatile(
        "mma.sync.aligned.m16n8k16.row.col.f32.bf16.bf16.f32 "
        "{%0,%1,%2,%3}, {%4,%5,%6,%7}, {%8,%9}, {%0,%1,%2,%3};\n"
        : "+f"(c[0]), "+f"(c[1]), "+f"(c[2]), "+f"(c[3])
        : "r"(a0), "r"(a1), "r"(a2), "r"(a3), "r"(b0), "r"(b1));
}

__device__ __forceinline__ unsigned pack_bf2(__nv_bfloat16 a, __nv_bfloat16 b) {
    __nv_bfloat162 p = __halves2bfloat162(a, b);
    return *reinterpret_cast<unsigned*>(&p);
}

#define GBM 128
// h[N,64] = combine( f[N,576] @ W'[576,192] ) via 3x bf16-split mma.sync
__global__ __launch_bounds__(512, 1) void k_gemm(int l, const float* __restrict__ convb) {
    // padded rows of 24 bf16 (48B) -> conflict-free frag loads
    __shared__ __align__(16) __nv_bfloat16 AsH[128 * 24];
    __shared__ __align__(16) __nv_bfloat16 AsL[128 * 24];
    __shared__ __align__(16) __nv_bfloat16 BsH[192 * 24];
    __shared__ __align__(16) __nv_bfloat16 BsL[192 * 24];

    int t = threadIdx.x;
    int rowBase = blockIdx.x * GBM;
    int lane = t & 31, warp = t >> 5;
    int wm = (warp >> 1) * 16;       // warp m offset (0..112)
    int wc = warp & 1;               // warp n-half (final cols 32*wc..)
    int r = lane >> 2, tg = lane & 3;

    // A staging: one float4 per thread
    int arow = t >> 2, ac4 = t & 3;
    int grow = rowBase + arow;
    float hasv = (grow < NN) ? g_has[grow] : 0.f;

    const uint4* Wb = reinterpret_cast<const uint4*>(g_Wb) + (size_t)(l * KSTEPS) * 768;

    float acc[12][4];
#pragma unroll
    for (int j = 0; j < 12; j++)
#pragma unroll
        for (int q = 0; q < 4; q++) acc[j][q] = 0.f;

    float4 va = make_float4(0.f, 0.f, 0.f, 0.f);
    uint4 vb0, vb1;
    vb1 = make_uint4(0u, 0u, 0u, 0u);
    // ---- prefetch kstep 0 ----
    {
        const float* src = g_x;
        if (grow < NN) {
            va = *(const float4*)(src + (size_t)grow * 64 + ac4 * 4);
            va.x *= hasv; va.y *= hasv; va.z *= hasv; va.w *= hasv;
        }
        vb0 = Wb[t];
        if (t < 256) vb1 = Wb[512 + t];
    }

    for (int kt = 0; kt < KSTEPS; kt++) {
        __syncthreads();
        // ---- store staged tile to smem (with A fp32 -> hi/lo split) ----
        {
            __nv_bfloat16 hx = __float2bfloat16_rn(va.x);
            __nv_bfloat16 hy = __float2bfloat16_rn(va.y);
            __nv_bfloat16 hz = __float2bfloat16_rn(va.z);
            __nv_bfloat16 hw = __float2bfloat16_rn(va.w);
            __nv_bfloat16 lx = __float2bfloat16_rn(va.x - __bfloat162float(hx));
            __nv_bfloat16 ly = __float2bfloat16_rn(va.y - __bfloat162float(hy));
            __nv_bfloat16 lz = __float2bfloat16_rn(va.z - __bfloat162float(hz));
            __nv_bfloat16 lw = __float2bfloat16_rn(va.w - __bfloat162float(hw));
            uint2 uh = make_uint2(pack_bf2(hx, hy), pack_bf2(hz, hw));
            uint2 ul = make_uint2(pack_bf2(lx, ly), pack_bf2(lz, lw));
            *reinterpret_cast<uint2*>(AsH + arow * 24 + ac4 * 4) = uh;
            *reinterpret_cast<uint2*>(AsL + arow * 24 + ac4 * 4) = ul;
            // B: uint4 i -> (hl, n, half)
            int i0 = t;
            int hl0 = (i0 >= 384);
            int rem0 = i0 - (hl0 ? 384 : 0);
            __nv_bfloat16* bp0 = (hl0 ? BsL : BsH) + (rem0 >> 1) * 24 + (rem0 & 1) * 8;
            *reinterpret_cast<uint4*>(bp0) = vb0;
            if (t < 256) {
                int i1 = 512 + t;
                int rem1 = i1 - 384;  // always lo
                __nv_bfloat16* bp1 = BsL + (rem1 >> 1) * 24 + (rem1 & 1) * 8;
                *reinterpret_cast<uint4*>(bp1) = vb1;
            }
        }
        __syncthreads();
        // ---- prefetch next kstep into registers (overlaps mma) ----
        if (kt + 1 < KSTEPS) {
            int k0 = (kt + 1) * 16;
            const float* src;
            int stride;
            bool msk = false;
            if (k0 < 64) { src = g_x + k0; stride = 64; msk = true; }
            else if (k0 < 320) { src = g_sagg + (k0 - 64); stride = 256; }
            else { src = g_eagg + (k0 - 320); stride = 256; }
            if (grow < NN) {
                va = *(const float4*)(src + (size_t)grow * stride + ac4 * 4);
                if (msk) { va.x *= hasv; va.y *= hasv; va.z *= hasv; va.w *= hasv; }
            } else {
                va = make_float4(0.f, 0.f, 0.f, 0.f);
            }
            const uint4* bp = Wb + (size_t)(kt + 1) * 768;
            vb0 = bp[t];
            if (t < 256) vb1 = bp[512 + t];
        }
        // ---- compute ----
        {
            const __nv_bfloat16* ah = AsH + (wm + r) * 24 + 2 * tg;
            const __nv_bfloat16* alp = AsL + (wm + r) * 24 + 2 * tg;
            unsigned a0 = *reinterpret_cast<const unsigned*>(ah);
            unsigned a1 = *reinterpret_cast<const unsigned*>(ah + 8 * 24);
            unsigned a2 = *reinterpret_cast<const unsigned*>(ah + 8);
            unsigned a3 = *reinterpret_cast<const unsigned*>(ah + 8 * 24 + 8);
            unsigned l0 = *reinterpret_cast<const unsigned*>(alp);
            unsigned l1 = *reinterpret_cast<const unsigned*>(alp + 8 * 24);
            unsigned l2 = *reinterpret_cast<const unsigned*>(alp + 8);
            unsigned l3 = *reinterpret_cast<const unsigned*>(alp + 8 * 24 + 8);
#pragma unroll
            for (int g = 0; g < 3; g++) {
#pragma unroll
                for (int jj = 0; jj < 4; jj++) {
                    int n0 = g * 64 + wc * 32 + jj * 8;
                    const __nv_bfloat16* bh = BsH + (n0 + r) * 24 + 2 * tg;
                    const __nv_bfloat16* bl = BsL + (n0 + r) * 24 + 2 * tg;
                    unsigned bh0 = *reinterpret_cast<const unsigned*>(bh);
                    unsigned bh1 = *reinterpret_cast<const unsigned*>(bh + 8);
                    unsigned bl0 = *reinterpret_cast<const unsigned*>(bl);
                    unsigned bl1 = *reinterpret_cast<const unsigned*>(bl + 8);
                    float* c = acc[g * 4 + jj];
                    mma16816(c, a0, a1, a2, a3, bh0, bh1);
                    mma16816(c, a0, a1, a2, a3, bl0, bl1);
                    mma16816(c, l0, l1, l2, l3, bh0, bh1);
                }
            }
        }
    }

    // ---- epilogue: combine plain + amp + att in registers ----
    int row0 = rowBase + wm + r;
    int row1 = row0 + 8;
    float amp0 = 0.f, att0 = 0.f, amp1 = 0.f, att1 = 0.f;
    if (row0 < NN) { amp0 = g_amp[row0]; att0 = g_att[row0]; }
    if (row1 < NN) { amp1 = g_amp[row1]; att1 = g_att[row1]; }
    const float* cst = g_cstd + l * JW;
#pragma unroll
    for (int jj = 0; jj < 4; jj++) {
        int c0 = wc * 32 + jj * 8 + 2 * tg;
#pragma unroll
        for (int e = 0; e < 2; e++) {
            int c = c0 + e;
            float cP = cst[c], cA = cst[64 + c], cT = cst[128 + c];
            float cb = convb[l * 64 + c];
            if (row0 < NN) {
                float h = acc[jj][e] + amp0 * acc[4 + jj][e] + att0 * acc[8 + jj][e]
                        + cP + amp0 * cA + att0 * cT + cb;
                g_h[(size_t)row0 * 64 + c] = h;
            }
            if (row1 < NN) {
                float h = acc[jj][2 + e] + amp1 * acc[4 + jj][2 + e] + att1 * acc[8 + jj][2 + e]
                        + cP + amp1 * cA + att1 * cT + cb;
                g_h[(size_t)row1 * 64 + c] = h;
            }
        }
    }
}

__global__ void k_bnzero() {
    int t = threadIdx.x;
    if (t < HH) { g_bnsum[t] = 0.f; g_bnss[t] = 0.f; }
}

__global__ void k_bnstats() {
    __shared__ float sh[512];
    int t = threadIdx.x;
    int c = t & 63, rg = t >> 6;
    float s = 0.f, ss = 0.f;
    int r0 = blockIdx.x * 256;
    for (int r = r0 + rg; r < r0 + 256 && r < NN; r += 4) {
        float v = g_h[(size_t)r * 64 + c];
        s += v;
        ss += v * v;
    }
    sh[t] = s; sh[256 + t] = ss;
    __syncthreads();
    if (rg == 0) {
        float S = sh[c] + sh[64 + c] + sh[128 + c] + sh[192 + c];
        float SS = sh[256 + c] + sh[320 + c] + sh[384 + c] + sh[448 + c];
        atomicAdd(&g_bnsum[c], S);
        atomicAdd(&g_bnss[c], SS);
    }
}

__global__ void k_bnapply(int l, const float* __restrict__ bg, const float* __restrict__ bb) {
    int idx = blockIdx.x * 256 + threadIdx.x;
    if (idx >= NN * HH) return;
    int c = idx & 63;
    float mu = g_bnsum[c] * (1.f / (float)NN);
    float var = fmaxf(g_bnss[c] * (1.f / (float)NN) - mu * mu, 0.f);
    float rs = rsqrtf(var + 1e-5f);
    float v = (g_h[idx] - mu) * rs * bg[l * 64 + c] + bb[l * 64 + c];
    g_x[idx] = fmaxf(v, 0.f) + g_x[idx];
}

__global__ void k_pool(const int* __restrict__ batch) {
    int idx = blockIdx.x * 256 + threadIdx.x;
    if (idx >= NN * HH) return;
    int n = idx >> 6, c = idx & 63;
    int b = batch[n];
    atomicAdd(&g_pool[b * 64 + c], g_x[idx]);
    if (c == 0) atomicAdd(&g_cnt[b], 1.f);
}

__global__ void k_fc(const float* __restrict__ w1, const float* __restrict__ b1,
                     const float* __restrict__ w2, const float* __restrict__ b2,
                     const float* __restrict__ w3, const float* __restrict__ b3,
                     float* __restrict__ out) {
    int g = threadIdx.x;
    if (g >= NGR) return;
    float v[64];
    float cnt = fmaxf(g_cnt[g], 1.f);
    float inv = 1.f / cnt;
    for (int d = 0; d < 64; d++) v[d] = g_pool[g * 64 + d] * inv;
    float h1[32];
    for (int o = 0; o < 32; o++) {
        float a = b1[o];
        for (int k = 0; k < 64; k++) a += v[k] * w1[k * 32 + o];
        h1[o] = fmaxf(a, 0.f);
    }
    float h2[16];
    for (int o = 0; o < 16; o++) {
        float a = b2[o];
        for (int k = 0; k < 32; k++) a += h1[k] * w2[k * 16 + o];
        h2[o] = fmaxf(a, 0.f);
    }
    for (int o = 0; o < NCLS; o++) {
        float a = b3[o];
        for (int k = 0; k < 16; k++) a += h2[k] * w3[k * 10 + o];
        out[g * NCLS + o] = a;
    }
}

// ------------------------------- launcher ------------------------------------
extern "C" void kernel_launch(void* const* d_in, const int* in_sizes, int n_in,
                              void* d_out, int out_size) {
    const float* xin   = (const float*)d_in[0];
    const int*   ei    = (const int*)d_in[1];
    const int*   batch = (const int*)d_in[2];
    const float* eattr = (const float*)d_in[3];
    const float* nw    = (const float*)d_in[4];
    const float* nb    = (const float*)d_in[5];
    const float* ew    = (const float*)d_in[6];
    const float* eb    = (const float*)d_in[7];
    const float* cw    = (const float*)d_in[8];
    const float* cb    = (const float*)d_in[9];
    const float* bg    = (const float*)d_in[10];
    const float* bb    = (const float*)d_in[11];
    const float* f1w   = (const float*)d_in[12];
    const float* f1b   = (const float*)d_in[13];
    const float* f2w   = (const float*)d_in[14];
    const float* f2b   = (const float*)d_in[15];
    const float* f3w   = (const float*)d_in[16];
    const float* f3b   = (const float*)d_in[17];
    float* out = (float*)d_out;

    const int NB_N = (NN + 255) / 256;
    const int NB_E = (EE + 255) / 256;
    const int NB_NE = (NN + 63) / 64;
    const int NB_W = (NN + 7) / 8;
    const int NB_ND = (NN * HH + 255) / 256;

    k_init<<<NB_N, 256>>>();
    k_nodeenc<<<NB_NE, 256>>>(xin, nw, nb);
    k_deghist<<<NB_E, 256>>>(ei);
    k_scanA<<<NB_N, 256>>>();
    k_scanB<<<1, 256>>>(NB_N);
    k_scanC<<<NB_N, 256>>>();
    k_csr<<<NB_E, 256>>>(ei);
    k_degstuff<<<NB_N, 256>>>();
    k_ampatt<<<NB_N, 256>>>();
    k_eagg<<<NB_W, 256>>>(eattr, ew, eb);
    k_wprep<<<(NLYR * KF * JW + 255) / 256, 256>>>(cw);
    k_cstd<<<(NLYR * JW + 63) / 64, 64>>>(cw);

    for (int l = 0; l < NLYR; l++) {
        k_srcagg<<<NB_W, 256>>>();
        k_gemm<<<(NN + GBM - 1) / GBM, 512>>>(l, cb);
        k_bnzero<<<1, 64>>>();
        k_bnstats<<<NB_N, 256>>>();
        k_bnapply<<<NB_ND, 256>>>(l, bg, bb);
    }

    k_pool<<<NB_ND, 256>>>(batch);
    k_fc<<<1, 64>>>(f1w, f1b, f2w, f2b, f3w, f3b, out);
}

// round 10
// speedup vs baseline: 1.7164x; 1.1671x over previous
#include <cuda_runtime.h>
#include <cuda_bf16.h>
#include <math.h>
#include <stdint.h>

#define NN 50000
#define NPAD 50048
#define EE 800000
#define HH 64
#define NLYR 3
#define NCLS 10
#define NGR 64
#define KF 576           // folded GEMM K: 64 (x) + 256 (src agg) + 256 (ea agg)
#define JW 192           // folded GEMM output cols: [plain | amp | att] x 64

// ------------------------- scratch (device globals, no allocs) ---------------
__device__ __align__(128) float g_x[NN * HH];        // current node features
__device__ __align__(128) float g_h[NN * HH];        // pre-BN layer output
// bf16 hi/lo activation matrix f[NPAD, 576]: [0:64)=x*has, [64:320)=srcagg, [320:576)=eagg
__device__ __align__(128) __nv_bfloat16 g_aggH[(size_t)NPAD * KF];
__device__ __align__(128) __nv_bfloat16 g_aggL[(size_t)NPAD * KF];
// folded weights bf16 hi/lo, n-major: [l][n=192][k=576]
__device__ __align__(128) __nv_bfloat16 g_WbH[NLYR * JW * KF];
__device__ __align__(128) __nv_bfloat16 g_WbL[NLYR * JW * KF];
__device__ float g_cstd[NLYR * JW];                  // std-dst constant contribution
__device__ int   g_degI[NN];
__device__ int   g_incl[NN];
__device__ int   g_bsumI[256];
__device__ int   g_boff[256];
__device__ int   g_rowptr[NN];
__device__ int   g_cursor[NN];
__device__ int   g_csrc[EE];
__device__ int   g_ceid[EE];
__device__ float g_has[NN];
__device__ float g_logdeg[NN];
__device__ float g_amp[NN];
__device__ float g_att[NN];
__device__ float g_logsum;
__device__ float g_bnsum[HH];
__device__ float g_bnss[HH];
__device__ float g_pool[NGR * HH];
__device__ float g_cnt[NGR];

// ------------------------------- small helpers -------------------------------
__device__ __forceinline__ void store_hl(int n, int col, float v) {
    __nv_bfloat16 h = __float2bfloat16_rn(v);
    g_aggH[(size_t)n * KF + col] = h;
    g_aggL[(size_t)n * KF + col] = __float2bfloat16_rn(v - __bfloat162float(h));
}

// ------------------------------- kernels -------------------------------------

__global__ void k_init() {
    int i = blockIdx.x * 256 + threadIdx.x;
    if (i < NN) g_degI[i] = 0;
    if (i < NGR * HH) g_pool[i] = 0.f;
    if (i < NGR) g_cnt[i] = 0.f;
    if (i == 0) g_logsum = 0.f;
}

// x = x_in @ node_w + node_b   (64x64)
__global__ void k_nodeenc(const float* __restrict__ xin,
                          const float* __restrict__ nw,
                          const float* __restrict__ nb) {
    __shared__ float Ws[64 * 64];
    __shared__ float Xs[64 * 64];
    int t = threadIdx.x;
    int n0 = blockIdx.x * 64;
    for (int i = t; i < 4096; i += 256) Ws[i] = nw[i];
    for (int i = t; i < 4096; i += 256) {
        int r = i >> 6, k = i & 63;
        int n = n0 + r;
        Xs[i] = (n < NN) ? xin[n * 64 + k] : 0.f;
    }
    __syncthreads();
    for (int p = 0; p < 16; p++) {
        int o = t + p * 256;
        int r = o >> 6, d = o & 63;
        float acc = nb[d];
#pragma unroll
        for (int k = 0; k < 64; k++) acc += Xs[r * 64 + k] * Ws[k * 64 + d];
        int n = n0 + r;
        if (n < NN) g_x[n * 64 + d] = acc;
    }
}

__global__ void k_deghist(const int* __restrict__ ei) {
    int e = blockIdx.x * 256 + threadIdx.x;
    if (e < EE) atomicAdd(&g_degI[ei[EE + e]], 1);
}

__global__ void k_scanA() {
    __shared__ int sh[256];
    int t = threadIdx.x;
    int n = blockIdx.x * 256 + t;
    int v = (n < NN) ? g_degI[n] : 0;
    sh[t] = v;
    __syncthreads();
    for (int off = 1; off < 256; off <<= 1) {
        int u = (t >= off) ? sh[t - off] : 0;
        __syncthreads();
        sh[t] += u;
        __syncthreads();
    }
    if (n < NN) g_incl[n] = sh[t];
    if (t == 255) g_bsumI[blockIdx.x] = sh[255];
}

__global__ void k_scanB(int nb) {
    __shared__ int sh[256];
    int t = threadIdx.x;
    int v = (t < nb) ? g_bsumI[t] : 0;
    sh[t] = v;
    __syncthreads();
    for (int off = 1; off < 256; off <<= 1) {
        int u = (t >= off) ? sh[t - off] : 0;
        __syncthreads();
        sh[t] += u;
        __syncthreads();
    }
    g_boff[t] = sh[t] - v;  // exclusive
}

__global__ void k_scanC() {
    int n = blockIdx.x * 256 + threadIdx.x;
    if (n < NN) {
        int rp = g_boff[n >> 8] + g_incl[n] - g_degI[n];
        g_rowptr[n] = rp;
        g_cursor[n] = rp;
    }
}

__global__ void k_csr(const int* __restrict__ ei) {
    int e = blockIdx.x * 256 + threadIdx.x;
    if (e < EE) {
        int dst = ei[EE + e];
        int p = atomicAdd(&g_cursor[dst], 1);
        g_csrc[p] = ei[e];
        g_ceid[p] = e;
    }
}

__global__ void k_degstuff() {
    __shared__ float sh[256];
    int t = threadIdx.x;
    int n = blockIdx.x * 256 + t;
    float part = 0.f;
    if (n < NN) {
        int d = g_degI[n];
        float df = (float)d;
        float degc = fmaxf(df, 1.f);
        g_has[n] = (d > 0) ? 1.f : 0.f;
        float ld = logf(degc + 1.f);
        g_logdeg[n] = ld;
        part = logf(df + 1.f);
    }
    sh[t] = part;
    __syncthreads();
    for (int off = 128; off; off >>= 1) {
        if (t < off) sh[t] += sh[t + off];
        __syncthreads();
    }
    if (t == 0) atomicAdd(&g_logsum, sh[0]);
}

__global__ void k_ampatt() {
    int n = blockIdx.x * 256 + threadIdx.x;
    if (n < NN) {
        float avg = g_logsum * (1.f / (float)NN);
        float ld = g_logdeg[n];
        g_amp[n] = ld / avg;
        g_att[n] = avg / ld;
    }
}

// layer-0 x split into g_agg cols [0:64)
__global__ void k_xsplit() {
    int idx = blockIdx.x * 256 + threadIdx.x;
    if (idx >= NN * HH) return;
    int n = idx >> 6, c = idx & 63;
    store_hl(n, c, g_x[idx] * g_has[n]);
}

// one-time edge-attr aggregation: ea = attr@edge_w + edge_b computed on the fly
__global__ void k_eagg(const float* __restrict__ eattr,
                       const float* __restrict__ ew,
                       const float* __restrict__ eb) {
    __shared__ float Ws[16 * 64];
    __shared__ float Bs[64];
    int t = threadIdx.x;
    for (int i = t; i < 1024; i += 256) Ws[i] = ew[i];
    if (t < 64) Bs[t] = eb[t];
    __syncthreads();
    int w = t >> 5, lane = t & 31;
    int n = blockIdx.x * 8 + w;
    if (n >= NN) return;
    int start = g_rowptr[n], deg = g_degI[n];
    int d0 = lane, d1 = lane + 32;
    float b0 = Bs[d0], b1 = Bs[d1];
    float s0 = 0.f, ss0 = 0.f, mx0 = -1e30f, mn0 = 1e30f;
    float s1 = 0.f, ss1 = 0.f, mx1 = -1e30f, mn1 = 1e30f;
    for (int i = 0; i < deg; i++) {
        int e = g_ceid[start + i];
        float av = (lane < 16) ? eattr[(size_t)e * 16 + lane] : 0.f;
        float v0 = b0, v1 = b1;
#pragma unroll
        for (int k = 0; k < 16; k++) {
            float a = __shfl_sync(0xffffffffu, av, k);
            v0 += a * Ws[k * 64 + d0];
            v1 += a * Ws[k * 64 + d1];
        }
        s0 += v0; ss0 += v0 * v0; mx0 = fmaxf(mx0, v0); mn0 = fminf(mn0, v0);
        s1 += v1; ss1 += v1 * v1; mx1 = fmaxf(mx1, v1); mn1 = fminf(mn1, v1);
    }
    float inv = 1.f / fmaxf((float)deg, 1.f);
    float m0 = s0 * inv, m1 = s1 * inv;
    float sd0 = sqrtf(fmaxf(ss0 * inv - m0 * m0, 0.f) + 1e-5f);
    float sd1 = sqrtf(fmaxf(ss1 * inv - m1 * m1, 0.f) + 1e-5f);
    if (deg == 0) { mx0 = 0.f; mn0 = 0.f; mx1 = 0.f; mn1 = 0.f; }
    store_hl(n, 320 + d0, m0);        store_hl(n, 320 + d1, m1);
    store_hl(n, 384 + d0, mn0);       store_hl(n, 384 + d1, mn1);
    store_hl(n, 448 + d0, mx0);       store_hl(n, 448 + d1, mx1);
    store_hl(n, 512 + d0, sd0);       store_hl(n, 512 + d1, sd1);
}

// per-layer src aggregation (x is L2-resident), writes bf16 hi/lo to g_agg
__global__ void k_srcagg() {
    int t = threadIdx.x;
    int w = t >> 5, lane = t & 31;
    int n = blockIdx.x * 8 + w;
    if (n >= NN) return;
    int start = g_rowptr[n], deg = g_degI[n];
    int d0 = lane, d1 = lane + 32;
    float s0 = 0.f, ss0 = 0.f, mx0 = -1e30f, mn0 = 1e30f;
    float s1 = 0.f, ss1 = 0.f, mx1 = -1e30f, mn1 = 1e30f;
    for (int i = 0; i < deg; i++) {
        int s = g_csrc[start + i];
        float v0 = g_x[(size_t)s * 64 + d0];
        float v1 = g_x[(size_t)s * 64 + d1];
        s0 += v0; ss0 += v0 * v0; mx0 = fmaxf(mx0, v0); mn0 = fminf(mn0, v0);
        s1 += v1; ss1 += v1 * v1; mx1 = fmaxf(mx1, v1); mn1 = fminf(mn1, v1);
    }
    float inv = 1.f / fmaxf((float)deg, 1.f);
    float m0 = s0 * inv, m1 = s1 * inv;
    float sd0 = sqrtf(fmaxf(ss0 * inv - m0 * m0, 0.f) + 1e-5f);
    float sd1 = sqrtf(fmaxf(ss1 * inv - m1 * m1, 0.f) + 1e-5f);
    if (deg == 0) { mx0 = 0.f; mn0 = 0.f; mx1 = 0.f; mn1 = 0.f; }
    store_hl(n, 64 + d0, m0);         store_hl(n, 64 + d1, m1);
    store_hl(n, 128 + d0, mn0);       store_hl(n, 128 + d1, mn1);
    store_hl(n, 192 + d0, mx0);       store_hl(n, 192 + d1, mx1);
    store_hl(n, 256 + d0, sd0);       store_hl(n, 256 + d1, sd1);
}

// fold conv_w [2304,64] -> W' [576,192], split bf16 hi/lo, n-major [192,576]
__global__ void k_wprep(const float* __restrict__ cw) {
    int idx = blockIdx.x * 256 + threadIdx.x;
    if (idx >= NLYR * KF * JW) return;
    int l = idx / (KF * JW);
    int r = idx % (KF * JW);
    int k = r / JW;
    int j = r % JW;
    int blk = j >> 6, c = j & 63;
    size_t base = (size_t)l * 2304 * 64;
    int R = blk * 768;
    float w;
    if (k < 64) {
        int d = k;
        w = cw[base + (size_t)(R + d) * 64 + c]
          + cw[base + (size_t)(R + 192 + d) * 64 + c]
          + cw[base + (size_t)(R + 384 + d) * 64 + c];
    } else if (k < 128) { int d = k - 64;  w = cw[base + (size_t)(R + 64 + d) * 64 + c]; }
    else if (k < 192)   { int d = k - 128; w = cw[base + (size_t)(R + 256 + d) * 64 + c]; }
    else if (k < 256)   { int d = k - 192; w = cw[base + (size_t)(R + 448 + d) * 64 + c]; }
    else if (k < 320)   { int d = k - 256; w = cw[base + (size_t)(R + 640 + d) * 64 + c]; }
    else if (k < 384)   { int d = k - 320; w = cw[base + (size_t)(R + 128 + d) * 64 + c]; }
    else if (k < 448)   { int d = k - 384; w = cw[base + (size_t)(R + 320 + d) * 64 + c]; }
    else if (k < 512)   { int d = k - 448; w = cw[base + (size_t)(R + 512 + d) * 64 + c]; }
    else                { int d = k - 512; w = cw[base + (size_t)(R + 704 + d) * 64 + c]; }
    __nv_bfloat16 hi = __float2bfloat16_rn(w);
    float lof = w - __bfloat162float(hi);
    size_t ob = ((size_t)l * JW + j) * KF + k;
    g_WbH[ob] = hi;
    g_WbL[ob] = __float2bfloat16_rn(lof);
}

__global__ void k_cstd(const float* __restrict__ cw) {
    int idx = blockIdx.x * 64 + threadIdx.x;
    if (idx >= NLYR * JW) return;
    int l = idx / JW;
    int j = idx % JW;
    int blk = j >> 6, c = j & 63;
    size_t base = (size_t)l * 2304 * 64;
    int R = blk * 768 + 576;
    float s = 0.f;
    for (int d = 0; d < 64; d++) s += cw[base + (size_t)(R + d) * 64 + c];
    g_cstd[idx] = sqrtf(1e-5f) * s;
}

// --------------------- HMMA v2 folded GEMM -----------------------------------
__device__ __forceinline__ uint32_t smem_u32(const void* p) {
    uint32_t a;
    asm("{ .reg .u64 t; cvta.to.shared.u64 t, %1; cvt.u32.u64 %0, t; }" : "=r"(a) : "l"(p));
    return a;
}
__device__ __forceinline__ void cpa16(uint32_t dst, const void* src) {
    asm volatile("cp.async.cg.shared.global [%0], [%1], 16;\n" :: "r"(dst), "l"(src));
}
__device__ __forceinline__ void ldsm4(uint32_t addr, unsigned& r0, unsigned& r1,
                                      unsigned& r2, unsigned& r3) {
    asm volatile("ldmatrix.sync.aligned.m8n8.x4.shared.b16 {%0,%1,%2,%3}, [%4];"
                 : "=r"(r0), "=r"(r1), "=r"(r2), "=r"(r3) : "r"(addr));
}
__device__ __forceinline__ void mma16816(float* c, unsigned a0, unsigned a1,
                                         unsigned a2, unsigned a3,
                                         unsigned b0, unsigned b1) {
    asm volatile(
        "mma.sync.aligned.m16n8k16.row.col.f32.bf16.bf16.f32 "
        "{%0,%1,%2,%3}, {%4,%5,%6,%7}, {%8,%9}, {%0,%1,%2,%3};\n"
        : "+f"(c[0]), "+f"(c[1]), "+f"(c[2]), "+f"(c[3])
        : "r"(a0), "r"(a1), "r"(a2), "r"(a3), "r"(b0), "r"(b1));
}

// smem layout per buffer (bytes): AH 0 (128x40 bf16 =10240), AL 10240,
// BH 20480 (192x40 =15360), BL 35840. Buffer stride 51200, x2 = 102400.
#define SMBUF 51200
#define SM_AL_OFF 10240
#define SM_BH_OFF 20480
#define SM_BL_OFF 35840
#define SM_TOTAL 102400
#define GBM 128
#define NKIT 18      // 576 / 32

__global__ void __launch_bounds__(512, 1) k_gemm2(int l, const float* __restrict__ convb) {
    extern __shared__ __align__(128) char dynsm[];
    uint32_t sb = smem_u32(dynsm);
    int t = threadIdx.x;
    int lane = t & 31, warp = t >> 5;
    int wm = (warp >> 1) * 16;   // warp m offset 0..112
    int wc = warp & 1;           // n half within each 64-group
    int r = lane >> 2, tg = lane & 3;
    int rowBase = blockIdx.x * GBM;

    const __nv_bfloat16* WH = g_WbH + (size_t)l * JW * KF;
    const __nv_bfloat16* WL = g_WbL + (size_t)l * JW * KF;

    float acc[12][4];
#pragma unroll
    for (int j = 0; j < 12; j++)
#pragma unroll
        for (int q = 0; q < 4; q++) acc[j][q] = 0.f;

    // precomputed ldmatrix addresses (per-lane), updated by buffer offset
    int arow = wm + (lane & 15);
    uint32_t a_off = (uint32_t)(arow * 80 + ((lane >> 4) << 4));   // +16B for k-hi half
    // B: mat pair base; tile chosen per p in loop: n0 = (T>>2)*64 + wc*32 + (T&3)*8
    int bkhalf = (lane >> 3) & 1;
    int btile_sel = lane >> 4;    // 0 or 1 -> tile 2p + sel
    int brow_in = lane & 7;

    // ---- prologue: load k-chunk 0 into buffer 0 ----
    {
        int kb = 0;
        uint32_t base = sb;
#pragma unroll
        for (int u = t; u < 1024; u += 512) {
            int row = u >> 3, q = (u >> 1) & 3, hl = u & 1;
            const __nv_bfloat16* src = (hl ? g_aggL : g_aggH) + (size_t)(rowBase + row) * KF + kb + q * 8;
            cpa16(base + (hl ? SM_AL_OFF : 0) + row * 80 + q * 16, src);
        }
#pragma unroll
        for (int u = t; u < 1536; u += 512) {
            int row = u >> 3, q = (u >> 1) & 3, hl = u & 1;
            const __nv_bfloat16* src = (hl ? WL : WH) + (size_t)row * KF + kb + q * 8;
            cpa16(base + SM_BH_OFF + (hl ? (SM_BL_OFF - SM_BH_OFF) : 0) + row * 80 + q * 16, src);
        }
        asm volatile("cp.async.commit_group;" ::: "memory");
    }

    for (int kt = 0; kt < NKIT; kt++) {
        uint32_t cur = sb + (kt & 1) * SMBUF;
        if (kt + 1 < NKIT) {
            int kb = (kt + 1) * 32;
            uint32_t base = sb + ((kt + 1) & 1) * SMBUF;
#pragma unroll
            for (int u = t; u < 1024; u += 512) {
                int row = u >> 3, q = (u >> 1) & 3, hl = u & 1;
                const __nv_bfloat16* src = (hl ? g_aggL : g_aggH) + (size_t)(rowBase + row) * KF + kb + q * 8;
                cpa16(base + (hl ? SM_AL_OFF : 0) + row * 80 + q * 16, src);
            }
#pragma unroll
            for (int u = t; u < 1536; u += 512) {
                int row = u >> 3, q = (u >> 1) & 3, hl = u & 1;
                const __nv_bfloat16* src = (hl ? WL : WH) + (size_t)row * KF + kb + q * 8;
                cpa16(base + SM_BH_OFF + (hl ? (SM_BL_OFF - SM_BH_OFF) : 0) + row * 80 + q * 16, src);
            }
            asm volatile("cp.async.commit_group;" ::: "memory");
            asm volatile("cp.async.wait_group 1;" ::: "memory");
        } else {
            asm volatile("cp.async.wait_group 0;" ::: "memory");
        }
        __syncthreads();

        // ---- compute on cur: two k16 sub-steps ----
#pragma unroll
        for (int kk = 0; kk < 2; kk++) {
            uint32_t k16b = kk * 32;   // 16 bf16 = 32 bytes
            unsigned a0, a1, a2, a3, l0, l1, l2, l3;
            ldsm4(cur + a_off + k16b, a0, a1, a2, a3);
            ldsm4(cur + SM_AL_OFF + a_off + k16b, l0, l1, l2, l3);
#pragma unroll
            for (int p = 0; p < 6; p++) {
                int T = 2 * p + btile_sel;
                int n0 = (T >> 2) * 64 + wc * 32 + (T & 3) * 8;
                uint32_t b_off = (uint32_t)((n0 + brow_in) * 80 + bkhalf * 16) + k16b;
                unsigned bh0, bh1, bh2, bh3, bl0, bl1, bl2, bl3;
                ldsm4(cur + SM_BH_OFF + b_off, bh0, bh1, bh2, bh3);
                ldsm4(cur + SM_BL_OFF + b_off, bl0, bl1, bl2, bl3);
                float* c0 = acc[2 * p];
                float* c1 = acc[2 * p + 1];
                mma16816(c0, a0, a1, a2, a3, bh0, bh1);
                mma16816(c1, a0, a1, a2, a3, bh2, bh3);
                mma16816(c0, a0, a1, a2, a3, bl0, bl1);
                mma16816(c1, a0, a1, a2, a3, bl2, bl3);
                mma16816(c0, l0, l1, l2, l3, bh0, bh1);
                mma16816(c1, l0, l1, l2, l3, bh2, bh3);
            }
        }
        __syncthreads();
    }

    // ---- epilogue: combine plain + amp + att in registers ----
    int row0 = rowBase + wm + r;
    int row1 = row0 + 8;
    float amp0 = 0.f, att0 = 0.f, amp1 = 0.f, att1 = 0.f;
    if (row0 < NN) { amp0 = g_amp[row0]; att0 = g_att[row0]; }
    if (row1 < NN) { amp1 = g_amp[row1]; att1 = g_att[row1]; }
    const float* cst = g_cstd + l * JW;
#pragma unroll
    for (int jj = 0; jj < 4; jj++) {
        int c0 = wc * 32 + jj * 8 + 2 * tg;
#pragma unroll
        for (int e = 0; e < 2; e++) {
            int c = c0 + e;
            float cP = cst[c], cA = cst[64 + c], cT = cst[128 + c];
            float cb = convb[l * 64 + c];
            if (row0 < NN) {
                float h = acc[jj][e] + amp0 * acc[4 + jj][e] + att0 * acc[8 + jj][e]
                        + cP + amp0 * cA + att0 * cT + cb;
                g_h[(size_t)row0 * 64 + c] = h;
            }
            if (row1 < NN) {
                float h = acc[jj][2 + e] + amp1 * acc[4 + jj][2 + e] + att1 * acc[8 + jj][2 + e]
                        + cP + amp1 * cA + att1 * cT + cb;
                g_h[(size_t)row1 * 64 + c] = h;
            }
        }
    }
}

__global__ void k_bnzero() {
    int t = threadIdx.x;
    if (t < HH) { g_bnsum[t] = 0.f; g_bnss[t] = 0.f; }
}

__global__ void k_bnstats() {
    __shared__ float sh[512];
    int t = threadIdx.x;
    int c = t & 63, rg = t >> 6;
    float s = 0.f, ss = 0.f;
    int r0 = blockIdx.x * 256;
    for (int r = r0 + rg; r < r0 + 256 && r < NN; r += 4) {
        float v = g_h[(size_t)r * 64 + c];
        s += v;
        ss += v * v;
    }
    sh[t] = s; sh[256 + t] = ss;
    __syncthreads();
    if (rg == 0) {
        float S = sh[c] + sh[64 + c] + sh[128 + c] + sh[192 + c];
        float SS = sh[256 + c] + sh[320 + c] + sh[384 + c] + sh[448 + c];
        atomicAdd(&g_bnsum[c], S);
        atomicAdd(&g_bnss[c], SS);
    }
}

// BN + relu + residual; also emits next layer's x*has bf16 split into g_agg[0:64)
__global__ void k_bnapply(int l, const float* __restrict__ bg, const float* __restrict__ bb) {
    int idx = blockIdx.x * 256 + threadIdx.x;
    if (idx >= NN * HH) return;
    int n = idx >> 6, c = idx & 63;
    float mu = g_bnsum[c] * (1.f / (float)NN);
    float var = fmaxf(g_bnss[c] * (1.f / (float)NN) - mu * mu, 0.f);
    float rs = rsqrtf(var + 1e-5f);
    float v = (g_h[idx] - mu) * rs * bg[l * 64 + c] + bb[l * 64 + c];
    float nx = fmaxf(v, 0.f) + g_x[idx];
    g_x[idx] = nx;
    store_hl(n, c, nx * g_has[n]);
}

__global__ void k_pool(const int* __restrict__ batch) {
    int idx = blockIdx.x * 256 + threadIdx.x;
    if (idx >= NN * HH) return;
    int n = idx >> 6, c = idx & 63;
    int b = batch[n];
    atomicAdd(&g_pool[b * 64 + c], g_x[idx]);
    if (c == 0) atomicAdd(&g_cnt[b], 1.f);
}

__global__ void k_fc(const float* __restrict__ w1, const float* __restrict__ b1,
                     const float* __restrict__ w2, const float* __restrict__ b2,
                     const float* __restrict__ w3, const float* __restrict__ b3,
                     float* __restrict__ out) {
    int g = threadIdx.x;
    if (g >= NGR) return;
    float v[64];
    float cnt = fmaxf(g_cnt[g], 1.f);
    float inv = 1.f / cnt;
    for (int d = 0; d < 64; d++) v[d] = g_pool[g * 64 + d] * inv;
    float h1[32];
    for (int o = 0; o < 32; o++) {
        float a = b1[o];
        for (int k = 0; k < 64; k++) a += v[k] * w1[k * 32 + o];
        h1[o] = fmaxf(a, 0.f);
    }
    float h2[16];
    for (int o = 0; o < 16; o++) {
        float a = b2[o];
        for (int k = 0; k < 32; k++) a += h1[k] * w2[k * 16 + o];
        h2[o] = fmaxf(a, 0.f);
    }
    for (int o = 0; o < NCLS; o++) {
        float a = b3[o];
        for (int k = 0; k < 16; k++) a += h2[k] * w3[k * 10 + o];
        out[g * NCLS + o] = a;
    }
}

// ------------------------------- launcher ------------------------------------
extern "C" void kernel_launch(void* const* d_in, const int* in_sizes, int n_in,
                              void* d_out, int out_size) {
    const float* xin   = (const float*)d_in[0];
    const int*   ei    = (const int*)d_in[1];
    const int*   batch = (const int*)d_in[2];
    const float* eattr = (const float*)d_in[3];
    const float* nw    = (const float*)d_in[4];
    const float* nb    = (const float*)d_in[5];
    const float* ew    = (const float*)d_in[6];
    const float* eb    = (const float*)d_in[7];
    const float* cw    = (const float*)d_in[8];
    const float* cb    = (const float*)d_in[9];
    const float* bg    = (const float*)d_in[10];
    const float* bb    = (const float*)d_in[11];
    const float* f1w   = (const float*)d_in[12];
    const float* f1b   = (const float*)d_in[13];
    const float* f2w   = (const float*)d_in[14];
    const float* f2b   = (const float*)d_in[15];
    const float* f3w   = (const float*)d_in[16];
    const float* f3b   = (const float*)d_in[17];
    float* out = (float*)d_out;

    cudaFuncSetAttribute(k_gemm2, cudaFuncAttributeMaxDynamicSharedMemorySize, SM_TOTAL);

    const int NB_N = (NN + 255) / 256;
    const int NB_E = (EE + 255) / 256;
    const int NB_NE = (NN + 63) / 64;
    const int NB_W = (NN + 7) / 8;
    const int NB_ND = (NN * HH + 255) / 256;
    const int NB_G = (NN + GBM - 1) / GBM;   // 391

    k_init<<<NB_N, 256>>>();
    k_nodeenc<<<NB_NE, 256>>>(xin, nw, nb);
    k_deghist<<<NB_E, 256>>>(ei);
    k_scanA<<<NB_N, 256>>>();
    k_scanB<<<1, 256>>>(NB_N);
    k_scanC<<<NB_N, 256>>>();
    k_csr<<<NB_E, 256>>>(ei);
    k_degstuff<<<NB_N, 256>>>();
    k_ampatt<<<NB_N, 256>>>();
    k_xsplit<<<NB_ND, 256>>>();
    k_eagg<<<NB_W, 256>>>(eattr, ew, eb);
    k_wprep<<<(NLYR * KF * JW + 255) / 256, 256>>>(cw);
    k_cstd<<<(NLYR * JW + 63) / 64, 64>>>(cw);

    for (int l = 0; l < NLYR; l++) {
        k_srcagg<<<NB_W, 256>>>();
        k_gemm2<<<NB_G, 512, SM_TOTAL>>>(l, cb);
        k_bnzero<<<1, 64>>>();
        k_bnstats<<<NB_N, 256>>>();
        k_bnapply<<<NB_ND, 256>>>(l, bg, bb);
    }

    k_pool<<<NB_ND, 256>>>(batch);
    k_fc<<<1, 64>>>(f1w, f1b, f2w, f2b, f3w, f3b, out);
}

// round 11
// speedup vs baseline: 1.8615x; 1.0845x over previous
#include <cuda_runtime.h>
#include <cuda_bf16.h>
#include <math.h>
#include <stdint.h>

#define NN 50000
#define NPAD 50048
#define EE 800000
#define HH 64
#define NLYR 3
#define NCLS 10
#define NGR 64
#define KF 576           // folded GEMM K: 64 (x) + 256 (src agg) + 256 (ea agg)
#define JW 192           // folded GEMM output cols: [plain | amp | att] x 64

// ------------------------- scratch (device globals, no allocs) ---------------
__device__ __align__(128) float g_x[NN * HH];        // current node features
__device__ __align__(128) float g_h[NN * HH];        // pre-BN layer output
// bf16 hi/lo activation matrix f[NPAD, 576]: [0:64)=x*has, [64:320)=srcagg, [320:576)=eagg
__device__ __align__(128) __nv_bfloat16 g_aggH[(size_t)NPAD * KF];
__device__ __align__(128) __nv_bfloat16 g_aggL[(size_t)NPAD * KF];
// folded weights bf16 hi/lo, n-major: [l][n=192][k=576]
__device__ __align__(128) __nv_bfloat16 g_WbH[NLYR * JW * KF];
__device__ __align__(128) __nv_bfloat16 g_WbL[NLYR * JW * KF];
__device__ float g_cstd[NLYR * JW];                  // std-dst constant contribution
__device__ int   g_degI[NN];
__device__ int   g_incl[NN];
__device__ int   g_bsumI[256];
__device__ int   g_boff[256];
__device__ int   g_rowptr[NN];
__device__ int   g_cursor[NN];
__device__ int   g_csrc[EE];
__device__ int   g_ceid[EE];
__device__ float g_has[NN];
__device__ float g_logdeg[NN];
__device__ float g_amp[NN];
__device__ float g_att[NN];
__device__ float g_logsum;
__device__ float g_bnsum[HH];
__device__ float g_bnss[HH];
__device__ float g_pool[NGR * HH];
__device__ float g_cnt[NGR];

// ------------------------------- small helpers -------------------------------
__device__ __forceinline__ void store_hl(int n, int col, float v) {
    __nv_bfloat16 h = __float2bfloat16_rn(v);
    g_aggH[(size_t)n * KF + col] = h;
    g_aggL[(size_t)n * KF + col] = __float2bfloat16_rn(v - __bfloat162float(h));
}

// ------------------------------- kernels -------------------------------------

__global__ void k_init() {
    int i = blockIdx.x * 256 + threadIdx.x;
    if (i < NN) g_degI[i] = 0;
    if (i < NGR * HH) g_pool[i] = 0.f;
    if (i < NGR) g_cnt[i] = 0.f;
    if (i == 0) g_logsum = 0.f;
}

// x = x_in @ node_w + node_b   (64x64)
__global__ void k_nodeenc(const float* __restrict__ xin,
                          const float* __restrict__ nw,
                          const float* __restrict__ nb) {
    __shared__ float Ws[64 * 64];
    __shared__ float Xs[64 * 64];
    int t = threadIdx.x;
    int n0 = blockIdx.x * 64;
    for (int i = t; i < 4096; i += 256) Ws[i] = nw[i];
    for (int i = t; i < 4096; i += 256) {
        int r = i >> 6, k = i & 63;
        int n = n0 + r;
        Xs[i] = (n < NN) ? xin[n * 64 + k] : 0.f;
    }
    __syncthreads();
    for (int p = 0; p < 16; p++) {
        int o = t + p * 256;
        int r = o >> 6, d = o & 63;
        float acc = nb[d];
#pragma unroll
        for (int k = 0; k < 64; k++) acc += Xs[r * 64 + k] * Ws[k * 64 + d];
        int n = n0 + r;
        if (n < NN) g_x[n * 64 + d] = acc;
    }
}

__global__ void k_deghist(const int* __restrict__ ei) {
    int e = blockIdx.x * 256 + threadIdx.x;
    if (e < EE) atomicAdd(&g_degI[ei[EE + e]], 1);
}

__global__ void k_scanA() {
    __shared__ int sh[256];
    int t = threadIdx.x;
    int n = blockIdx.x * 256 + t;
    int v = (n < NN) ? g_degI[n] : 0;
    sh[t] = v;
    __syncthreads();
    for (int off = 1; off < 256; off <<= 1) {
        int u = (t >= off) ? sh[t - off] : 0;
        __syncthreads();
        sh[t] += u;
        __syncthreads();
    }
    if (n < NN) g_incl[n] = sh[t];
    if (t == 255) g_bsumI[blockIdx.x] = sh[255];
}

__global__ void k_scanB(int nb) {
    __shared__ int sh[256];
    int t = threadIdx.x;
    int v = (t < nb) ? g_bsumI[t] : 0;
    sh[t] = v;
    __syncthreads();
    for (int off = 1; off < 256; off <<= 1) {
        int u = (t >= off) ? sh[t - off] : 0;
        __syncthreads();
        sh[t] += u;
        __syncthreads();
    }
    g_boff[t] = sh[t] - v;  // exclusive
}

__global__ void k_scanC() {
    int n = blockIdx.x * 256 + threadIdx.x;
    if (n < NN) {
        int rp = g_boff[n >> 8] + g_incl[n] - g_degI[n];
        g_rowptr[n] = rp;
        g_cursor[n] = rp;
    }
}

__global__ void k_csr(const int* __restrict__ ei) {
    int e = blockIdx.x * 256 + threadIdx.x;
    if (e < EE) {
        int dst = ei[EE + e];
        int p = atomicAdd(&g_cursor[dst], 1);
        g_csrc[p] = ei[e];
        g_ceid[p] = e;
    }
}

__global__ void k_degstuff() {
    __shared__ float sh[256];
    int t = threadIdx.x;
    int n = blockIdx.x * 256 + t;
    float part = 0.f;
    if (n < NN) {
        int d = g_degI[n];
        float df = (float)d;
        float degc = fmaxf(df, 1.f);
        g_has[n] = (d > 0) ? 1.f : 0.f;
        float ld = logf(degc + 1.f);
        g_logdeg[n] = ld;
        part = logf(df + 1.f);
    }
    sh[t] = part;
    __syncthreads();
    for (int off = 128; off; off >>= 1) {
        if (t < off) sh[t] += sh[t + off];
        __syncthreads();
    }
    if (t == 0) atomicAdd(&g_logsum, sh[0]);
}

// amp/att + per-graph node counting (fused; g_cnt zeroed in k_init)
__global__ void k_ampatt(const int* __restrict__ batch) {
    int n = blockIdx.x * 256 + threadIdx.x;
    if (n < NN) {
        float avg = g_logsum * (1.f / (float)NN);
        float ld = g_logdeg[n];
        g_amp[n] = ld / avg;
        g_att[n] = avg / ld;
        atomicAdd(&g_cnt[batch[n]], 1.f);
    }
}

// layer-0 x split into g_agg cols [0:64)
__global__ void k_xsplit() {
    int idx = blockIdx.x * 256 + threadIdx.x;
    if (idx >= NN * HH) return;
    int n = idx >> 6, c = idx & 63;
    store_hl(n, c, g_x[idx] * g_has[n]);
}

// one-time edge-attr aggregation: ea = attr@edge_w + edge_b computed on the fly
__global__ void k_eagg(const float* __restrict__ eattr,
                       const float* __restrict__ ew,
                       const float* __restrict__ eb) {
    __shared__ float Ws[16 * 64];
    __shared__ float Bs[64];
    int t = threadIdx.x;
    for (int i = t; i < 1024; i += 256) Ws[i] = ew[i];
    if (t < 64) Bs[t] = eb[t];
    __syncthreads();
    int w = t >> 5, lane = t & 31;
    int n = blockIdx.x * 8 + w;
    if (n >= NN) return;
    int start = g_rowptr[n], deg = g_degI[n];
    int d0 = lane, d1 = lane + 32;
    float b0 = Bs[d0], b1 = Bs[d1];
    float s0 = 0.f, ss0 = 0.f, mx0 = -1e30f, mn0 = 1e30f;
    float s1 = 0.f, ss1 = 0.f, mx1 = -1e30f, mn1 = 1e30f;
    for (int i = 0; i < deg; i++) {
        int e = g_ceid[start + i];
        float av = (lane < 16) ? eattr[(size_t)e * 16 + lane] : 0.f;
        float v0 = b0, v1 = b1;
#pragma unroll
        for (int k = 0; k < 16; k++) {
            float a = __shfl_sync(0xffffffffu, av, k);
            v0 += a * Ws[k * 64 + d0];
            v1 += a * Ws[k * 64 + d1];
        }
        s0 += v0; ss0 += v0 * v0; mx0 = fmaxf(mx0, v0); mn0 = fminf(mn0, v0);
        s1 += v1; ss1 += v1 * v1; mx1 = fmaxf(mx1, v1); mn1 = fminf(mn1, v1);
    }
    float inv = 1.f / fmaxf((float)deg, 1.f);
    float m0 = s0 * inv, m1 = s1 * inv;
    float sd0 = sqrtf(fmaxf(ss0 * inv - m0 * m0, 0.f) + 1e-5f);
    float sd1 = sqrtf(fmaxf(ss1 * inv - m1 * m1, 0.f) + 1e-5f);
    if (deg == 0) { mx0 = 0.f; mn0 = 0.f; mx1 = 0.f; mn1 = 0.f; }
    store_hl(n, 320 + d0, m0);        store_hl(n, 320 + d1, m1);
    store_hl(n, 384 + d0, mn0);       store_hl(n, 384 + d1, mn1);
    store_hl(n, 448 + d0, mx0);       store_hl(n, 448 + d1, mx1);
    store_hl(n, 512 + d0, sd0);       store_hl(n, 512 + d1, sd1);
}

// per-layer src aggregation (x is L2-resident), writes bf16 hi/lo to g_agg.
// Block 0 also zeroes the BN accumulators for this layer (runs before bnstats).
__global__ void k_srcagg() {
    int t = threadIdx.x;
    if (blockIdx.x == 0 && t < 64) { g_bnsum[t] = 0.f; g_bnss[t] = 0.f; }
    int w = t >> 5, lane = t & 31;
    int n = blockIdx.x * 8 + w;
    if (n >= NN) return;
    int start = g_rowptr[n], deg = g_degI[n];
    int d0 = lane, d1 = lane + 32;
    float s0 = 0.f, ss0 = 0.f, mx0 = -1e30f, mn0 = 1e30f;
    float s1 = 0.f, ss1 = 0.f, mx1 = -1e30f, mn1 = 1e30f;
    for (int i = 0; i < deg; i++) {
        int s = g_csrc[start + i];
        float v0 = g_x[(size_t)s * 64 + d0];
        float v1 = g_x[(size_t)s * 64 + d1];
        s0 += v0; ss0 += v0 * v0; mx0 = fmaxf(mx0, v0); mn0 = fminf(mn0, v0);
        s1 += v1; ss1 += v1 * v1; mx1 = fmaxf(mx1, v1); mn1 = fminf(mn1, v1);
    }
    float inv = 1.f / fmaxf((float)deg, 1.f);
    float m0 = s0 * inv, m1 = s1 * inv;
    float sd0 = sqrtf(fmaxf(ss0 * inv - m0 * m0, 0.f) + 1e-5f);
    float sd1 = sqrtf(fmaxf(ss1 * inv - m1 * m1, 0.f) + 1e-5f);
    if (deg == 0) { mx0 = 0.f; mn0 = 0.f; mx1 = 0.f; mn1 = 0.f; }
    store_hl(n, 64 + d0, m0);         store_hl(n, 64 + d1, m1);
    store_hl(n, 128 + d0, mn0);       store_hl(n, 128 + d1, mn1);
    store_hl(n, 192 + d0, mx0);       store_hl(n, 192 + d1, mx1);
    store_hl(n, 256 + d0, sd0);       store_hl(n, 256 + d1, sd1);
}

// fold conv_w [2304,64] -> W' [576,192], split bf16 hi/lo, n-major [192,576]
__global__ void k_wprep(const float* __restrict__ cw) {
    int idx = blockIdx.x * 256 + threadIdx.x;
    if (idx >= NLYR * KF * JW) return;
    int l = idx / (KF * JW);
    int r = idx % (KF * JW);
    int k = r / JW;
    int j = r % JW;
    int blk = j >> 6, c = j & 63;
    size_t base = (size_t)l * 2304 * 64;
    int R = blk * 768;
    float w;
    if (k < 64) {
        int d = k;
        w = cw[base + (size_t)(R + d) * 64 + c]
          + cw[base + (size_t)(R + 192 + d) * 64 + c]
          + cw[base + (size_t)(R + 384 + d) * 64 + c];
    } else if (k < 128) { int d = k - 64;  w = cw[base + (size_t)(R + 64 + d) * 64 + c]; }
    else if (k < 192)   { int d = k - 128; w = cw[base + (size_t)(R + 256 + d) * 64 + c]; }
    else if (k < 256)   { int d = k - 192; w = cw[base + (size_t)(R + 448 + d) * 64 + c]; }
    else if (k < 320)   { int d = k - 256; w = cw[base + (size_t)(R + 640 + d) * 64 + c]; }
    else if (k < 384)   { int d = k - 320; w = cw[base + (size_t)(R + 128 + d) * 64 + c]; }
    else if (k < 448)   { int d = k - 384; w = cw[base + (size_t)(R + 320 + d) * 64 + c]; }
    else if (k < 512)   { int d = k - 448; w = cw[base + (size_t)(R + 512 + d) * 64 + c]; }
    else                { int d = k - 512; w = cw[base + (size_t)(R + 704 + d) * 64 + c]; }
    __nv_bfloat16 hi = __float2bfloat16_rn(w);
    float lof = w - __bfloat162float(hi);
    size_t ob = ((size_t)l * JW + j) * KF + k;
    g_WbH[ob] = hi;
    g_WbL[ob] = __float2bfloat16_rn(lof);
}

__global__ void k_cstd(const float* __restrict__ cw) {
    int idx = blockIdx.x * 64 + threadIdx.x;
    if (idx >= NLYR * JW) return;
    int l = idx / JW;
    int j = idx % JW;
    int blk = j >> 6, c = j & 63;
    size_t base = (size_t)l * 2304 * 64;
    int R = blk * 768 + 576;
    float s = 0.f;
    for (int d = 0; d < 64; d++) s += cw[base + (size_t)(R + d) * 64 + c];
    g_cstd[idx] = sqrtf(1e-5f) * s;
}

// --------------------- HMMA v3 folded GEMM (deep pipeline) -------------------
__device__ __forceinline__ uint32_t smem_u32(const void* p) {
    uint32_t a;
    asm("{ .reg .u64 t; cvta.to.shared.u64 t, %1; cvt.u32.u64 %0, t; }" : "=r"(a) : "l"(p));
    return a;
}
__device__ __forceinline__ void cpa16(uint32_t dst, const void* src) {
    asm volatile("cp.async.cg.shared.global [%0], [%1], 16;\n" :: "r"(dst), "l"(src));
}
__device__ __forceinline__ void ldsm4(uint32_t addr, unsigned& r0, unsigned& r1,
                                      unsigned& r2, unsigned& r3) {
    asm volatile("ldmatrix.sync.aligned.m8n8.x4.shared.b16 {%0,%1,%2,%3}, [%4];"
                 : "=r"(r0), "=r"(r1), "=r"(r2), "=r"(r3) : "r"(addr));
}
__device__ __forceinline__ void mma16816(float* c, unsigned a0, unsigned a1,
                                         unsigned a2, unsigned a3,
                                         unsigned b0, unsigned b1) {
    asm volatile(
        "mma.sync.aligned.m16n8k16.row.col.f32.bf16.bf16.f32 "
        "{%0,%1,%2,%3}, {%4,%5,%6,%7}, {%8,%9}, {%0,%1,%2,%3};\n"
        : "+f"(c[0]), "+f"(c[1]), "+f"(c[2]), "+f"(c[3])
        : "r"(a0), "r"(a1), "r"(a2), "r"(a3), "r"(b0), "r"(b1));
}

// smem layout per buffer (bytes): AH 0 (128x40 bf16 =10240), AL 10240,
// BH 20480 (192x40 =15360), BL 35840. Buffer stride 51200, x4 = 204800.
#define SMBUF 51200
#define SM_AL_OFF 10240
#define SM_BH_OFF 20480
#define SM_BL_OFF 35840
#define SM_TOTAL 204800
#define GBM 128
#define NKIT 18      // 576 / 32

__global__ void __launch_bounds__(512, 1) k_gemm2(int l, const float* __restrict__ convb) {
    extern __shared__ __align__(128) char dynsm[];
    uint32_t sb = smem_u32(dynsm);
    int t = threadIdx.x;
    int lane = t & 31, warp = t >> 5;
    int wm = (warp >> 1) * 16;   // warp m offset 0..112
    int wc = warp & 1;           // n half within each 64-group
    int r = lane >> 2, tg = lane & 3;
    int rowBase = blockIdx.x * GBM;

    const __nv_bfloat16* WH = g_WbH + (size_t)l * JW * KF;
    const __nv_bfloat16* WL = g_WbL + (size_t)l * JW * KF;

    float acc[12][4];
#pragma unroll
    for (int j = 0; j < 12; j++)
#pragma unroll
        for (int q = 0; q < 4; q++) acc[j][q] = 0.f;

    // precomputed ldmatrix addresses (per-lane)
    int arow = wm + (lane & 15);
    uint32_t a_off = (uint32_t)(arow * 80 + ((lane >> 4) << 4));
    int bkhalf = (lane >> 3) & 1;
    int btile_sel = lane >> 4;
    int brow_in = lane & 7;

    // chunk loader: chunk idx -> buffer idx&3
#define LOAD_CHUNK(IDX) do {                                                        \
        int kb_ = (IDX) * 32;                                                       \
        uint32_t base_ = sb + (uint32_t)((IDX) & 3) * SMBUF;                        \
        _Pragma("unroll")                                                           \
        for (int u = t; u < 1024; u += 512) {                                       \
            int row = u >> 3, q = (u >> 1) & 3, hl = u & 1;                         \
            const __nv_bfloat16* src = (hl ? g_aggL : g_aggH)                       \
                + (size_t)(rowBase + row) * KF + kb_ + q * 8;                       \
            cpa16(base_ + (hl ? SM_AL_OFF : 0) + row * 80 + q * 16, src);           \
        }                                                                           \
        _Pragma("unroll")                                                           \
        for (int u = t; u < 1536; u += 512) {                                       \
            int row = u >> 3, q = (u >> 1) & 3, hl = u & 1;                         \
            const __nv_bfloat16* src = (hl ? WL : WH) + (size_t)row * KF + kb_ + q * 8; \
            cpa16(base_ + SM_BH_OFF + (hl ? (SM_BL_OFF - SM_BH_OFF) : 0)            \
                  + row * 80 + q * 16, src);                                        \
        }                                                                           \
        asm volatile("cp.async.commit_group;" ::: "memory");                        \
    } while (0)

    // ---- prologue: chunks 0 and 1 ----
    LOAD_CHUNK(0);
    LOAD_CHUNK(1);

    for (int kt = 0; kt < NKIT; kt++) {
        if (kt + 2 < NKIT) LOAD_CHUNK(kt + 2);
        if (kt < NKIT - 2) {
            asm volatile("cp.async.wait_group 2;" ::: "memory");
        } else if (kt == NKIT - 2) {
            asm volatile("cp.async.wait_group 1;" ::: "memory");
        } else {
            asm volatile("cp.async.wait_group 0;" ::: "memory");
        }
        __syncthreads();
        uint32_t cur = sb + (uint32_t)(kt & 3) * SMBUF;

        // ---- compute on cur: two k16 sub-steps ----
#pragma unroll
        for (int kk = 0; kk < 2; kk++) {
            uint32_t k16b = kk * 32;   // 16 bf16 = 32 bytes
            unsigned a0, a1, a2, a3, l0, l1, l2, l3;
            ldsm4(cur + a_off + k16b, a0, a1, a2, a3);
            ldsm4(cur + SM_AL_OFF + a_off + k16b, l0, l1, l2, l3);
#pragma unroll
            for (int p = 0; p < 6; p++) {
                int T = 2 * p + btile_sel;
                int n0 = (T >> 2) * 64 + wc * 32 + (T & 3) * 8;
                uint32_t b_off = (uint32_t)((n0 + brow_in) * 80 + bkhalf * 16) + k16b;
                unsigned bh0, bh1, bh2, bh3, bl0, bl1, bl2, bl3;
                ldsm4(cur + SM_BH_OFF + b_off, bh0, bh1, bh2, bh3);
                ldsm4(cur + SM_BL_OFF + b_off, bl0, bl1, bl2, bl3);
                float* c0 = acc[2 * p];
                float* c1 = acc[2 * p + 1];
                mma16816(c0, a0, a1, a2, a3, bh0, bh1);
                mma16816(c1, a0, a1, a2, a3, bh2, bh3);
                mma16816(c0, a0, a1, a2, a3, bl0, bl1);
                mma16816(c1, a0, a1, a2, a3, bl2, bl3);
                mma16816(c0, l0, l1, l2, l3, bh0, bh1);
                mma16816(c1, l0, l1, l2, l3, bh2, bh3);
            }
        }
    }
#undef LOAD_CHUNK

    // ---- epilogue: combine plain + amp + att in registers ----
    int row0 = rowBase + wm + r;
    int row1 = row0 + 8;
    float amp0 = 0.f, att0 = 0.f, amp1 = 0.f, att1 = 0.f;
    if (row0 < NN) { amp0 = g_amp[row0]; att0 = g_att[row0]; }
    if (row1 < NN) { amp1 = g_amp[row1]; att1 = g_att[row1]; }
    const float* cst = g_cstd + l * JW;
#pragma unroll
    for (int jj = 0; jj < 4; jj++) {
        int c0 = wc * 32 + jj * 8 + 2 * tg;
#pragma unroll
        for (int e = 0; e < 2; e++) {
            int c = c0 + e;
            float cP = cst[c], cA = cst[64 + c], cT = cst[128 + c];
            float cb = convb[l * 64 + c];
            if (row0 < NN) {
                float h = acc[jj][e] + amp0 * acc[4 + jj][e] + att0 * acc[8 + jj][e]
                        + cP + amp0 * cA + att0 * cT + cb;
                g_h[(size_t)row0 * 64 + c] = h;
            }
            if (row1 < NN) {
                float h = acc[jj][2 + e] + amp1 * acc[4 + jj][2 + e] + att1 * acc[8 + jj][2 + e]
                        + cP + amp1 * cA + att1 * cT + cb;
                g_h[(size_t)row1 * 64 + c] = h;
            }
        }
    }
}

__global__ void k_bnstats() {
    __shared__ float sh[512];
    int t = threadIdx.x;
    int c = t & 63, rg = t >> 6;
    float s = 0.f, ss = 0.f;
    int r0 = blockIdx.x * 256;
    for (int r = r0 + rg; r < r0 + 256 && r < NN; r += 4) {
        float v = g_h[(size_t)r * 64 + c];
        s += v;
        ss += v * v;
    }
    sh[t] = s; sh[256 + t] = ss;
    __syncthreads();
    if (rg == 0) {
        float S = sh[c] + sh[64 + c] + sh[128 + c] + sh[192 + c];
        float SS = sh[256 + c] + sh[320 + c] + sh[384 + c] + sh[448 + c];
        atomicAdd(&g_bnsum[c], S);
        atomicAdd(&g_bnss[c], SS);
    }
}

// BN + relu + residual. For inner layers: update g_x and emit next-layer x*has
// split. For the LAST layer: pool directly into g_pool (skips k_pool pass).
__global__ void k_bnapply(int l, const float* __restrict__ bg, const float* __restrict__ bb,
                          const int* __restrict__ batch, int last) {
    int idx = blockIdx.x * 256 + threadIdx.x;
    if (idx >= NN * HH) return;
    int n = idx >> 6, c = idx & 63;
    float mu = g_bnsum[c] * (1.f / (float)NN);
    float var = fmaxf(g_bnss[c] * (1.f / (float)NN) - mu * mu, 0.f);
    float rs = rsqrtf(var + 1e-5f);
    float v = (g_h[idx] - mu) * rs * bg[l * 64 + c] + bb[l * 64 + c];
    float nx = fmaxf(v, 0.f) + g_x[idx];
    if (last) {
        atomicAdd(&g_pool[batch[n] * 64 + c], nx);
    } else {
        g_x[idx] = nx;
        store_hl(n, c, nx * g_has[n]);
    }
}

__global__ void k_fc(const float* __restrict__ w1, const float* __restrict__ b1,
                     const float* __restrict__ w2, const float* __restrict__ b2,
                     const float* __restrict__ w3, const float* __restrict__ b3,
                     float* __restrict__ out) {
    int g = threadIdx.x;
    if (g >= NGR) return;
    float v[64];
    float cnt = fmaxf(g_cnt[g], 1.f);
    float inv = 1.f / cnt;
    for (int d = 0; d < 64; d++) v[d] = g_pool[g * 64 + d] * inv;
    float h1[32];
    for (int o = 0; o < 32; o++) {
        float a = b1[o];
        for (int k = 0; k < 64; k++) a += v[k] * w1[k * 32 + o];
        h1[o] = fmaxf(a, 0.f);
    }
    float h2[16];
    for (int o = 0; o < 16; o++) {
        float a = b2[o];
        for (int k = 0; k < 32; k++) a += h1[k] * w2[k * 16 + o];
        h2[o] = fmaxf(a, 0.f);
    }
    for (int o = 0; o < NCLS; o++) {
        float a = b3[o];
        for (int k = 0; k < 16; k++) a += h2[k] * w3[k * 10 + o];
        out[g * NCLS + o] = a;
    }
}

// ------------------------------- launcher ------------------------------------
extern "C" void kernel_launch(void* const* d_in, const int* in_sizes, int n_in,
                              void* d_out, int out_size) {
    const float* xin   = (const float*)d_in[0];
    const int*   ei    = (const int*)d_in[1];
    const int*   batch = (const int*)d_in[2];
    const float* eattr = (const float*)d_in[3];
    const float* nw    = (const float*)d_in[4];
    const float* nb    = (const float*)d_in[5];
    const float* ew    = (const float*)d_in[6];
    const float* eb    = (const float*)d_in[7];
    const float* cw    = (const float*)d_in[8];
    const float* cb    = (const float*)d_in[9];
    const float* bg    = (const float*)d_in[10];
    const float* bb    = (const float*)d_in[11];
    const float* f1w   = (const float*)d_in[12];
    const float* f1b   = (const float*)d_in[13];
    const float* f2w   = (const float*)d_in[14];
    const float* f2b   = (const float*)d_in[15];
    const float* f3w   = (const float*)d_in[16];
    const float* f3b   = (const float*)d_in[17];
    float* out = (float*)d_out;

    cudaFuncSetAttribute(k_gemm2, cudaFuncAttributeMaxDynamicSharedMemorySize, SM_TOTAL);

    const int NB_N = (NN + 255) / 256;
    const int NB_E = (EE + 255) / 256;
    const int NB_NE = (NN + 63) / 64;
    const int NB_W = (NN + 7) / 8;
    const int NB_ND = (NN * HH + 255) / 256;
    const int NB_G = (NN + GBM - 1) / GBM;   // 391

    k_init<<<NB_N, 256>>>();
    k_nodeenc<<<NB_NE, 256>>>(xin, nw, nb);
    k_deghist<<<NB_E, 256>>>(ei);
    k_scanA<<<NB_N, 256>>>();
    k_scanB<<<1, 256>>>(NB_N);
    k_scanC<<<NB_N, 256>>>();
    k_csr<<<NB_E, 256>>>(ei);
    k_degstuff<<<NB_N, 256>>>();
    k_ampatt<<<NB_N, 256>>>(batch);
    k_xsplit<<<NB_ND, 256>>>();
    k_eagg<<<NB_W, 256>>>(eattr, ew, eb);
    k_wprep<<<(NLYR * KF * JW + 255) / 256, 256>>>(cw);
    k_cstd<<<(NLYR * JW + 63) / 64, 64>>>(cw);

    for (int l = 0; l < NLYR; l++) {
        k_srcagg<<<NB_W, 256>>>();
        k_gemm2<<<NB_G, 512, SM_TOTAL>>>(l, cb);
        k_bnstats<<<NB_N, 256>>>();
        k_bnapply<<<NB_ND, 256>>>(l, bg, bb, batch, l == NLYR - 1);
    }

    k_fc<<<1, 64>>>(f1w, f1b, f2w, f2b, f3w, f3b, out);
}

// round 14
// speedup vs baseline: 2.0366x; 1.0941x over previous
#include <cuda_runtime.h>
#include <cuda_fp16.h>
#include <math.h>
#include <stdint.h>

#define NN 50000
#define NPAD 50048
#define EE 800000
#define HH 64
#define NLYR 3
#define NCLS 10
#define NGR 64
#define KF 576           // folded GEMM K: 64 (x) + 256 (src agg) + 256 (ea agg)
#define JW 192           // folded GEMM output cols: [plain | amp | att] x 64

// ------------------------- scratch (device globals, no allocs) ---------------
__device__ __align__(128) float g_x[NN * HH];        // current node features
__device__ __align__(128) float g_h[NN * HH];        // pre-BN layer output
// fp16 activation matrix f[NPAD, 576]: [0:64)=x*has, [64:320)=srcagg, [320:576)=eagg
__device__ __align__(128) __half g_aggH[(size_t)NPAD * KF];
// folded weights fp16 hi/lo, n-major: [l][n=192][k=576]
__device__ __align__(128) __half g_WbH[NLYR * JW * KF];
__device__ __align__(128) __half g_WbL[NLYR * JW * KF];
__device__ float g_cstd[NLYR * JW];                  // std-dst constant contribution
__device__ int   g_degI[NN];
__device__ int   g_incl[NN];
__device__ int   g_bsumI[256];
__device__ int   g_boff[256];
__device__ int   g_rowptr[NN];
__device__ int   g_cursor[NN];
__device__ int   g_csrc[EE];
__device__ int   g_ceid[EE];
__device__ float g_has[NN];
__device__ float g_logdeg[NN];
__device__ float g_amp[NN];
__device__ float g_att[NN];
__device__ float g_logsum;
__device__ float g_bnsum[HH];
__device__ float g_bnss[HH];
__device__ float g_pool[NGR * HH];
__device__ float g_cnt[NGR];

// ------------------------------- small helpers -------------------------------
__device__ __forceinline__ void store_h(int n, int col, float v) {
    g_aggH[(size_t)n * KF + col] = __float2half_rn(v);
}

// ------------------------------- kernels -------------------------------------

__global__ void k_init() {
    int i = blockIdx.x * 256 + threadIdx.x;
    if (i < NN) g_degI[i] = 0;
    if (i < NGR * HH) g_pool[i] = 0.f;
    if (i < NGR) g_cnt[i] = 0.f;
    if (i == 0) g_logsum = 0.f;
}

__global__ void k_deghist(const int* __restrict__ ei) {
    int e = blockIdx.x * 256 + threadIdx.x;
    if (e < EE) atomicAdd(&g_degI[ei[EE + e]], 1);
}

__global__ void k_scanA() {
    __shared__ int sh[256];
    int t = threadIdx.x;
    int n = blockIdx.x * 256 + t;
    int v = (n < NN) ? g_degI[n] : 0;
    sh[t] = v;
    __syncthreads();
    for (int off = 1; off < 256; off <<= 1) {
        int u = (t >= off) ? sh[t - off] : 0;
        __syncthreads();
        sh[t] += u;
        __syncthreads();
    }
    if (n < NN) g_incl[n] = sh[t];
    if (t == 255) g_bsumI[blockIdx.x] = sh[255];
}

__global__ void k_scanB(int nb) {
    __shared__ int sh[256];
    int t = threadIdx.x;
    int v = (t < nb) ? g_bsumI[t] : 0;
    sh[t] = v;
    __syncthreads();
    for (int off = 1; off < 256; off <<= 1) {
        int u = (t >= off) ? sh[t - off] : 0;
        __syncthreads();
        sh[t] += u;
        __syncthreads();
    }
    g_boff[t] = sh[t] - v;  // exclusive
}

__global__ void k_scanC() {
    int n = blockIdx.x * 256 + threadIdx.x;
    if (n < NN) {
        int rp = g_boff[n >> 8] + g_incl[n] - g_degI[n];
        g_rowptr[n] = rp;
        g_cursor[n] = rp;
    }
}

__global__ void k_csr(const int* __restrict__ ei) {
    int e = blockIdx.x * 256 + threadIdx.x;
    if (e < EE) {
        int dst = ei[EE + e];
        int p = atomicAdd(&g_cursor[dst], 1);
        g_csrc[p] = ei[e];
        g_ceid[p] = e;
    }
}

__global__ void k_degstuff() {
    __shared__ float sh[256];
    int t = threadIdx.x;
    int n = blockIdx.x * 256 + t;
    float part = 0.f;
    if (n < NN) {
        int d = g_degI[n];
        float df = (float)d;
        float degc = fmaxf(df, 1.f);
        g_has[n] = (d > 0) ? 1.f : 0.f;
        float ld = logf(degc + 1.f);
        g_logdeg[n] = ld;
        part = logf(df + 1.f);
    }
    sh[t] = part;
    __syncthreads();
    for (int off = 128; off; off >>= 1) {
        if (t < off) sh[t] += sh[t + off];
        __syncthreads();
    }
    if (t == 0) atomicAdd(&g_logsum, sh[0]);
}

// amp/att + per-graph node counting (fused; g_cnt zeroed in k_init)
__global__ void k_ampatt(const int* __restrict__ batch) {
    int n = blockIdx.x * 256 + threadIdx.x;
    if (n < NN) {
        float avg = g_logsum * (1.f / (float)NN);
        float ld = g_logdeg[n];
        g_amp[n] = ld / avg;
        g_att[n] = avg / ld;
        atomicAdd(&g_cnt[batch[n]], 1.f);
    }
}

// x = x_in @ node_w + node_b (64x64); also emits layer-0 x*has fp16 into g_agg[0:64)
__global__ void k_nodeenc(const float* __restrict__ xin,
                          const float* __restrict__ nw,
                          const float* __restrict__ nb) {
    __shared__ float Ws[64 * 64];
    __shared__ float Xs[64 * 64];
    int t = threadIdx.x;
    int n0 = blockIdx.x * 64;
    for (int i = t; i < 4096; i += 256) Ws[i] = nw[i];
    for (int i = t; i < 4096; i += 256) {
        int r = i >> 6, k = i & 63;
        int n = n0 + r;
        Xs[i] = (n < NN) ? xin[n * 64 + k] : 0.f;
    }
    __syncthreads();
    for (int p = 0; p < 16; p++) {
        int o = t + p * 256;
        int r = o >> 6, d = o & 63;
        float acc = nb[d];
#pragma unroll
        for (int k = 0; k < 64; k++) acc += Xs[r * 64 + k] * Ws[k * 64 + d];
        int n = n0 + r;
        if (n < NN) {
            g_x[n * 64 + d] = acc;
            store_h(n, d, acc * g_has[n]);
        }
    }
}

// one-time edge-attr aggregation: ea = attr@edge_w + edge_b computed on the fly
__global__ void k_eagg(const float* __restrict__ eattr,
                       const float* __restrict__ ew,
                       const float* __restrict__ eb) {
    __shared__ float Ws[16 * 64];
    __shared__ float Bs[64];
    int t = threadIdx.x;
    for (int i = t; i < 1024; i += 256) Ws[i] = ew[i];
    if (t < 64) Bs[t] = eb[t];
    __syncthreads();
    int w = t >> 5, lane = t & 31;
    int n = blockIdx.x * 8 + w;
    if (n >= NN) return;
    int start = g_rowptr[n], deg = g_degI[n];
    int d0 = lane, d1 = lane + 32;
    float b0 = Bs[d0], b1 = Bs[d1];
    float s0 = 0.f, ss0 = 0.f, mx0 = -1e30f, mn0 = 1e30f;
    float s1 = 0.f, ss1 = 0.f, mx1 = -1e30f, mn1 = 1e30f;
    for (int i = 0; i < deg; i++) {
        int e = g_ceid[start + i];
        float av = (lane < 16) ? eattr[(size_t)e * 16 + lane] : 0.f;
        float v0 = b0, v1 = b1;
#pragma unroll
        for (int k = 0; k < 16; k++) {
            float a = __shfl_sync(0xffffffffu, av, k);
            v0 += a * Ws[k * 64 + d0];
            v1 += a * Ws[k * 64 + d1];
        }
        s0 += v0; ss0 += v0 * v0; mx0 = fmaxf(mx0, v0); mn0 = fminf(mn0, v0);
        s1 += v1; ss1 += v1 * v1; mx1 = fmaxf(mx1, v1); mn1 = fminf(mn1, v1);
    }
    float inv = 1.f / fmaxf((float)deg, 1.f);
    float m0 = s0 * inv, m1 = s1 * inv;
    float sd0 = sqrtf(fmaxf(ss0 * inv - m0 * m0, 0.f) + 1e-5f);
    float sd1 = sqrtf(fmaxf(ss1 * inv - m1 * m1, 0.f) + 1e-5f);
    if (deg == 0) { mx0 = 0.f; mn0 = 0.f; mx1 = 0.f; mn1 = 0.f; }
    store_h(n, 320 + d0, m0);        store_h(n, 320 + d1, m1);
    store_h(n, 384 + d0, mn0);       store_h(n, 384 + d1, mn1);
    store_h(n, 448 + d0, mx0);       store_h(n, 448 + d1, mx1);
    store_h(n, 512 + d0, sd0);       store_h(n, 512 + d1, sd1);
}

// per-layer src aggregation (x is L2-resident), writes fp16 to g_agg.
// Block 0 also zeroes the BN accumulators for this layer (runs before gemm).
__global__ void k_srcagg() {
    int t = threadIdx.x;
    if (blockIdx.x == 0 && t < 64) { g_bnsum[t] = 0.f; g_bnss[t] = 0.f; }
    int w = t >> 5, lane = t & 31;
    int n = blockIdx.x * 8 + w;
    if (n >= NN) return;
    int start = g_rowptr[n], deg = g_degI[n];
    int d0 = lane, d1 = lane + 32;
    float s0 = 0.f, ss0 = 0.f, mx0 = -1e30f, mn0 = 1e30f;
    float s1 = 0.f, ss1 = 0.f, mx1 = -1e30f, mn1 = 1e30f;
    for (int i = 0; i < deg; i++) {
        int s = g_csrc[start + i];
        float v0 = g_x[(size_t)s * 64 + d0];
        float v1 = g_x[(size_t)s * 64 + d1];
        s0 += v0; ss0 += v0 * v0; mx0 = fmaxf(mx0, v0); mn0 = fminf(mn0, v0);
        s1 += v1; ss1 += v1 * v1; mx1 = fmaxf(mx1, v1); mn1 = fminf(mn1, v1);
    }
    float inv = 1.f / fmaxf((float)deg, 1.f);
    float m0 = s0 * inv, m1 = s1 * inv;
    float sd0 = sqrtf(fmaxf(ss0 * inv - m0 * m0, 0.f) + 1e-5f);
    float sd1 = sqrtf(fmaxf(ss1 * inv - m1 * m1, 0.f) + 1e-5f);
    if (deg == 0) { mx0 = 0.f; mn0 = 0.f; mx1 = 0.f; mn1 = 0.f; }
    store_h(n, 64 + d0, m0);         store_h(n, 64 + d1, m1);
    store_h(n, 128 + d0, mn0);       store_h(n, 128 + d1, mn1);
    store_h(n, 192 + d0, mx0);       store_h(n, 192 + d1, mx1);
    store_h(n, 256 + d0, sd0);       store_h(n, 256 + d1, sd1);
}

// fold conv_w [2304,64] -> W' [576,192], split fp16 hi/lo, n-major [192,576]
__global__ void k_wprep(const float* __restrict__ cw) {
    int idx = blockIdx.x * 256 + threadIdx.x;
    if (idx >= NLYR * KF * JW) return;
    int l = idx / (KF * JW);
    int r = idx % (KF * JW);
    int k = r / JW;
    int j = r % JW;
    int blk = j >> 6, c = j & 63;
    size_t base = (size_t)l * 2304 * 64;
    int R = blk * 768;
    float w;
    if (k < 64) {
        int d = k;
        w = cw[base + (size_t)(R + d) * 64 + c]
          + cw[base + (size_t)(R + 192 + d) * 64 + c]
          + cw[base + (size_t)(R + 384 + d) * 64 + c];
    } else if (k < 128) { int d = k - 64;  w = cw[base + (size_t)(R + 64 + d) * 64 + c]; }
    else if (k < 192)   { int d = k - 128; w = cw[base + (size_t)(R + 256 + d) * 64 + c]; }
    else if (k < 256)   { int d = k - 192; w = cw[base + (size_t)(R + 448 + d) * 64 + c]; }
    else if (k < 320)   { int d = k - 256; w = cw[base + (size_t)(R + 640 + d) * 64 + c]; }
    else if (k < 384)   { int d = k - 320; w = cw[base + (size_t)(R + 128 + d) * 64 + c]; }
    else if (k < 448)   { int d = k - 384; w = cw[base + (size_t)(R + 320 + d) * 64 + c]; }
    else if (k < 512)   { int d = k - 448; w = cw[base + (size_t)(R + 512 + d) * 64 + c]; }
    else                { int d = k - 512; w = cw[base + (size_t)(R + 704 + d) * 64 + c]; }
    __half hi = __float2half_rn(w);
    float lof = w - __half2float(hi);
    size_t ob = ((size_t)l * JW + j) * KF + k;
    g_WbH[ob] = hi;
    g_WbL[ob] = __float2half_rn(lof);
}

__global__ void k_cstd(const float* __restrict__ cw) {
    int idx = blockIdx.x * 64 + threadIdx.x;
    if (idx >= NLYR * JW) return;
    int l = idx / JW;
    int j = idx % JW;
    int blk = j >> 6, c = j & 63;
    size_t base = (size_t)l * 2304 * 64;
    int R = blk * 768 + 576;
    float s = 0.f;
    for (int d = 0; d < 64; d++) s += cw[base + (size_t)(R + d) * 64 + c];
    g_cstd[idx] = sqrtf(1e-5f) * s;
}

// --------------- HMMA v4 folded GEMM (fp16 2-term, fused BN stats) -----------
__device__ __forceinline__ uint32_t smem_u32(const void* p) {
    uint32_t a;
    asm("{ .reg .u64 t; cvta.to.shared.u64 t, %1; cvt.u32.u64 %0, t; }" : "=r"(a) : "l"(p));
    return a;
}
__device__ __forceinline__ void cpa16(uint32_t dst, const void* src) {
    asm volatile("cp.async.cg.shared.global [%0], [%1], 16;\n" :: "r"(dst), "l"(src));
}
__device__ __forceinline__ void ldsm4(uint32_t addr, unsigned& r0, unsigned& r1,
                                      unsigned& r2, unsigned& r3) {
    asm volatile("ldmatrix.sync.aligned.m8n8.x4.shared.b16 {%0,%1,%2,%3}, [%4];"
                 : "=r"(r0), "=r"(r1), "=r"(r2), "=r"(r3) : "r"(addr));
}
__device__ __forceinline__ void mma16816(float* c, unsigned a0, unsigned a1,
                                         unsigned a2, unsigned a3,
                                         unsigned b0, unsigned b1) {
    asm volatile(
        "mma.sync.aligned.m16n8k16.row.col.f32.f16.f16.f32 "
        "{%0,%1,%2,%3}, {%4,%5,%6,%7}, {%8,%9}, {%0,%1,%2,%3};\n"
        : "+f"(c[0]), "+f"(c[1]), "+f"(c[2]), "+f"(c[3])
        : "r"(a0), "r"(a1), "r"(a2), "r"(a3), "r"(b0), "r"(b1));
}

// smem per buffer: A 128x(32 fp16 = 64B data, 80B stride) = 10240,
// BH 192x80 = 15360, BL 15360 -> 40960. 4 buffers = 163840, + 512 stats.
#define SMBUF 40960
#define SM_BH_OFF 10240
#define SM_BL_OFF 25600
#define SM_STATS 163840
#define SM_TOTAL (163840 + 512)
#define GBM 128
#define NKIT 18      // 576 / 32

__global__ void __launch_bounds__(512, 1) k_gemm2(int l, const float* __restrict__ convb) {
    extern __shared__ __align__(128) char dynsm[];
    uint32_t sb = smem_u32(dynsm);
    float* s_sum = (float*)(dynsm + SM_STATS);
    float* s_ss = s_sum + 64;
    int t = threadIdx.x;
    int lane = t & 31, warp = t >> 5;
    int wm = (warp >> 1) * 16;   // warp m offset 0..112
    int wc = warp & 1;           // n half within each 64-group
    int r = lane >> 2, tg = lane & 3;
    int rowBase = blockIdx.x * GBM;

    const __half* WH = g_WbH + (size_t)l * JW * KF;
    const __half* WL = g_WbL + (size_t)l * JW * KF;

    float acc[12][4];
#pragma unroll
    for (int j = 0; j < 12; j++)
#pragma unroll
        for (int q = 0; q < 4; q++) acc[j][q] = 0.f;

    // ldmatrix addressing (per-lane)
    int arow = wm + (lane & 15);
    uint32_t a_off = (uint32_t)(arow * 80 + ((lane >> 4) << 4));
    int bkhalf = (lane >> 3) & 1;
    int btile_sel = lane >> 4;
    int brow_in = lane & 7;

#define LOAD_CHUNK(IDX) do {                                                        \
        int kb_ = (IDX) * 32;                                                       \
        uint32_t base_ = sb + (uint32_t)((IDX) & 3) * SMBUF;                        \
        { int row = t >> 2, q = t & 3;                                              \
          cpa16(base_ + row * 80 + q * 16,                                          \
                g_aggH + (size_t)(rowBase + row) * KF + kb_ + q * 8); }             \
        _Pragma("unroll")                                                           \
        for (int u = t; u < 1536; u += 512) {                                       \
            int hl = u & 1; int w2 = u >> 1; int row = w2 >> 2, q = w2 & 3;         \
            const __half* src = (hl ? WL : WH) + (size_t)row * KF + kb_ + q * 8;    \
            cpa16(base_ + SM_BH_OFF + hl * (SM_BL_OFF - SM_BH_OFF)                  \
                  + row * 80 + q * 16, src);                                        \
        }                                                                           \
        asm volatile("cp.async.commit_group;" ::: "memory");                        \
    } while (0)

    LOAD_CHUNK(0);
    LOAD_CHUNK(1);

    for (int kt = 0; kt < NKIT; kt++) {
        if (kt + 2 < NKIT) LOAD_CHUNK(kt + 2);
        if (kt < NKIT - 2) {
            asm volatile("cp.async.wait_group 2;" ::: "memory");
        } else if (kt == NKIT - 2) {
            asm volatile("cp.async.wait_group 1;" ::: "memory");
        } else {
            asm volatile("cp.async.wait_group 0;" ::: "memory");
        }
        __syncthreads();
        uint32_t cur = sb + (uint32_t)(kt & 3) * SMBUF;

#pragma unroll
        for (int kk = 0; kk < 2; kk++) {
            uint32_t k16b = kk * 32;   // 16 fp16 = 32 bytes
            unsigned a0, a1, a2, a3;
            ldsm4(cur + a_off + k16b, a0, a1, a2, a3);
#pragma unroll
            for (int p = 0; p < 6; p++) {
                int T = 2 * p + btile_sel;
                int n0 = (T >> 2) * 64 + wc * 32 + (T & 3) * 8;
                uint32_t b_off = (uint32_t)((n0 + brow_in) * 80 + bkhalf * 16) + k16b;
                unsigned bh0, bh1, bh2, bh3, bl0, bl1, bl2, bl3;
                ldsm4(cur + SM_BH_OFF + b_off, bh0, bh1, bh2, bh3);
                ldsm4(cur + SM_BL_OFF + b_off, bl0, bl1, bl2, bl3);
                float* c0 = acc[2 * p];
                float* c1 = acc[2 * p + 1];
                mma16816(c0, a0, a1, a2, a3, bh0, bh1);
                mma16816(c1, a0, a1, a2, a3, bh2, bh3);
                mma16816(c0, a0, a1, a2, a3, bl0, bl1);
                mma16816(c1, a0, a1, a2, a3, bl2, bl3);
            }
        }
    }
#undef LOAD_CHUNK

    // ---- epilogue: combine plain+amp+att, store h, fused BN stats ----
    __syncthreads();
    if (t < 64) { s_sum[t] = 0.f; s_ss[t] = 0.f; }
    __syncthreads();

    int row0 = rowBase + wm + r;
    int row1 = row0 + 8;
    float amp0 = 0.f, att0 = 0.f, amp1 = 0.f, att1 = 0.f;
    if (row0 < NN) { amp0 = g_amp[row0]; att0 = g_att[row0]; }
    if (row1 < NN) { amp1 = g_amp[row1]; att1 = g_att[row1]; }
    const float* cst = g_cstd + l * JW;
    float hs[8], hq[8];
#pragma unroll
    for (int jj = 0; jj < 4; jj++) {
        int c0 = wc * 32 + jj * 8 + 2 * tg;
#pragma unroll
        for (int e = 0; e < 2; e++) {
            int c = c0 + e;
            float cP = cst[c], cA = cst[64 + c], cT = cst[128 + c];
            float cb = convb[l * 64 + c];
            float h0v = 0.f, h1v = 0.f;
            if (row0 < NN) {
                h0v = acc[jj][e] + amp0 * acc[4 + jj][e] + att0 * acc[8 + jj][e]
                    + cP + amp0 * cA + att0 * cT + cb;
                g_h[(size_t)row0 * 64 + c] = h0v;
            }
            if (row1 < NN) {
                h1v = acc[jj][2 + e] + amp1 * acc[4 + jj][2 + e] + att1 * acc[8 + jj][2 + e]
                    + cP + amp1 * cA + att1 * cT + cb;
                g_h[(size_t)row1 * 64 + c] = h1v;
            }
            hs[jj * 2 + e] = h0v + h1v;
            hq[jj * 2 + e] = h0v * h0v + h1v * h1v;
        }
    }
    // reduce over m within warp (lanes sharing tg): xor over bits 2,3,4
#pragma unroll
    for (int s = 0; s < 8; s++) {
#pragma unroll
        for (int off = 4; off < 32; off <<= 1) {
            hs[s] += __shfl_xor_sync(0xffffffffu, hs[s], off);
            hq[s] += __shfl_xor_sync(0xffffffffu, hq[s], off);
        }
    }
    if (lane < 4) {
#pragma unroll
        for (int s = 0; s < 8; s++) {
            int c = wc * 32 + (s >> 1) * 8 + 2 * lane + (s & 1);
            atomicAdd(&s_sum[c], hs[s]);
            atomicAdd(&s_ss[c], hq[s]);
        }
    }
    __syncthreads();
    if (t < 64) {
        atomicAdd(&g_bnsum[t], s_sum[t]);
        atomicAdd(&g_bnss[t], s_ss[t]);
    }
}

// BN + relu + residual. Inner layers: update g_x + next-layer fp16 split.
// LAST layer: pool directly into g_pool.
__global__ void k_bnapply(int l, const float* __restrict__ bg, const float* __restrict__ bb,
                          const int* __restrict__ batch, int last) {
    int idx = blockIdx.x * 256 + threadIdx.x;
    if (idx >= NN * HH) return;
    int n = idx >> 6, c = idx & 63;
    float mu = g_bnsum[c] * (1.f / (float)NN);
    float var = fmaxf(g_bnss[c] * (1.f / (float)NN) - mu * mu, 0.f);
    float rs = rsqrtf(var + 1e-5f);
    float v = (g_h[idx] - mu) * rs * bg[l * 64 + c] + bb[l * 64 + c];
    float nx = fmaxf(v, 0.f) + g_x[idx];
    if (last) {
        atomicAdd(&g_pool[batch[n] * 64 + c], nx);
    } else {
        g_x[idx] = nx;
        store_h(n, c, nx * g_has[n]);
    }
}

__global__ void k_fc(const float* __restrict__ w1, const float* __restrict__ b1,
                     const float* __restrict__ w2, const float* __restrict__ b2,
                     const float* __restrict__ w3, const float* __restrict__ b3,
                     float* __restrict__ out) {
    int g = threadIdx.x;
    if (g >= NGR) return;
    float v[64];
    float cnt = fmaxf(g_cnt[g], 1.f);
    float inv = 1.f / cnt;
    for (int d = 0; d < 64; d++) v[d] = g_pool[g * 64 + d] * inv;
    float h1[32];
    for (int o = 0; o < 32; o++) {
        float a = b1[o];
        for (int k = 0; k < 64; k++) a += v[k] * w1[k * 32 + o];
        h1[o] = fmaxf(a, 0.f);
    }
    float h2[16];
    for (int o = 0; o < 16; o++) {
        float a = b2[o];
        for (int k = 0; k < 32; k++) a += h1[k] * w2[k * 16 + o];
        h2[o] = fmaxf(a, 0.f);
    }
    for (int o = 0; o < NCLS; o++) {
        float a = b3[o];
        for (int k = 0; k < 16; k++) a += h2[k] * w3[k * 10 + o];
        out[g * NCLS + o] = a;
    }
}

// ------------------------------- launcher ------------------------------------
extern "C" void kernel_launch(void* const* d_in, const int* in_sizes, int n_in,
                              void* d_out, int out_size) {
    const float* xin   = (const float*)d_in[0];
    const int*   ei    = (const int*)d_in[1];
    const int*   batch = (const int*)d_in[2];
    const float* eattr = (const float*)d_in[3];
    const float* nw    = (const float*)d_in[4];
    const float* nb    = (const float*)d_in[5];
    const float* ew    = (const float*)d_in[6];
    const float* eb    = (const float*)d_in[7];
    const float* cw    = (const float*)d_in[8];
    const float* cb    = (const float*)d_in[9];
    const float* bg    = (const float*)d_in[10];
    const float* bb    = (const float*)d_in[11];
    const float* f1w   = (const float*)d_in[12];
    const float* f1b   = (const float*)d_in[13];
    const float* f2w   = (const float*)d_in[14];
    const float* f2b   = (const float*)d_in[15];
    const float* f3w   = (const float*)d_in[16];
    const float* f3b   = (const float*)d_in[17];
    float* out = (float*)d_out;

    cudaFuncSetAttribute(k_gemm2, cudaFuncAttributeMaxDynamicSharedMemorySize, SM_TOTAL);

    const int NB_N = (NN + 255) / 256;
    const int NB_E = (EE + 255) / 256;
    const int NB_NE = (NN + 63) / 64;
    const int NB_W = (NN + 7) / 8;
    const int NB_ND = (NN * HH + 255) / 256;
    const int NB_G = (NN + GBM - 1) / GBM;   // 391

    k_init<<<NB_N, 256>>>();
    k_deghist<<<NB_E, 256>>>(ei);
    k_scanA<<<NB_N, 256>>>();
    k_scanB<<<1, 256>>>(NB_N);
    k_scanC<<<NB_N, 256>>>();
    k_csr<<<NB_E, 256>>>(ei);
    k_degstuff<<<NB_N, 256>>>();
    k_ampatt<<<NB_N, 256>>>(batch);
    k_nodeenc<<<NB_NE, 256>>>(xin, nw, nb);
    k_eagg<<<NB_W, 256>>>(eattr, ew, eb);
    k_wprep<<<(NLYR * KF * JW + 255) / 256, 256>>>(cw);
    k_cstd<<<(NLYR * JW + 63) / 64, 64>>>(cw);

    for (int l = 0; l < NLYR; l++) {
        k_srcagg<<<NB_W, 256>>>();
        k_gemm2<<<NB_G, 512, SM_TOTAL>>>(l, cb);
        k_bnapply<<<NB_ND, 256>>>(l, bg, bb, batch, l == NLYR - 1);
    }

    k_fc<<<1, 64>>>(f1w, f1b, f2w, f2b, f3w, f3b, out);
}